// round 7
// baseline (speedup 1.0000x reference)
#include <cuda_runtime.h>
#include <cuda_bf16.h>
#include <cstdint>

// Problem constants
#define NN   100000   // nodes
#define RR   4        // relations
#define EE   500000   // edges per relation
#define INF  256
#define HIDF 128
#define OUTF 64

// ---------------------------------------------------------------------------
// Static device scratch (allocation-free per harness rules)
// ---------------------------------------------------------------------------
static __device__ __nv_bfloat16 g_xhi[(size_t)NN * INF];     // 51.2 MB
static __device__ __nv_bfloat16 g_xlo[(size_t)NN * INF];     // 51.2 MB
static __device__ __nv_bfloat16 g_w1hi[RR * INF * HIDF];
static __device__ __nv_bfloat16 g_w1lo[RR * INF * HIDF];
static __device__ __nv_bfloat16 g_w2hi[RR * HIDF * OUTF];
static __device__ __nv_bfloat16 g_w2lo[RR * HIDF * OUTF];
static __device__ __nv_bfloat16 g_a2hi[(size_t)NN * HIDF];   // 25.6 MB
static __device__ __nv_bfloat16 g_a2lo[(size_t)NN * HIDF];   // 25.6 MB
static __device__ float g_Y1[(size_t)RR * NN * HIDF];        // 204.8 MB  [r][n][128]
static __device__ float g_Y2[(size_t)RR * NN * OUTF];        // 102.4 MB  [r][n][64]
static __device__ float g_acc1[(size_t)NN * HIDF];           // 51.2 MB
static __device__ float g_rs[2 * RR * NN];                   // [out | in]

// ---------------------------------------------------------------------------
// Tensor-core primitives (sm_80+ mma.sync, bf16 -> f32)
// ---------------------------------------------------------------------------
__device__ __forceinline__ void ldsm_x4(uint32_t* r, uint32_t a) {
    asm volatile("ldmatrix.sync.aligned.m8n8.x4.shared.b16 {%0,%1,%2,%3}, [%4];"
                 : "=r"(r[0]), "=r"(r[1]), "=r"(r[2]), "=r"(r[3]) : "r"(a));
}
__device__ __forceinline__ void ldsm_x2t(uint32_t* r, uint32_t a) {
    asm volatile("ldmatrix.sync.aligned.m8n8.x2.trans.shared.b16 {%0,%1}, [%2];"
                 : "=r"(r[0]), "=r"(r[1]) : "r"(a));
}
__device__ __forceinline__ void mma16816(float* c, const uint32_t* a, const uint32_t* b) {
    asm volatile(
        "mma.sync.aligned.m16n8k16.row.col.f32.bf16.bf16.f32 "
        "{%0,%1,%2,%3}, {%4,%5,%6,%7}, {%8,%9}, {%0,%1,%2,%3};"
        : "+f"(c[0]), "+f"(c[1]), "+f"(c[2]), "+f"(c[3])
        : "r"(a[0]), "r"(a[1]), "r"(a[2]), "r"(a[3]), "r"(b[0]), "r"(b[1]));
}

// ---------------------------------------------------------------------------
// Preprocessing kernels
// ---------------------------------------------------------------------------
__global__ void fzero_kernel(float* p, int n) {
    int i = blockIdx.x * blockDim.x + threadIdx.x;
    if (i < n) p[i] = 0.0f;
}

__global__ void degree_count_kernel(const int* __restrict__ src,
                                    const int* __restrict__ dst,
                                    float* __restrict__ rs_out,
                                    float* __restrict__ rs_in) {
    int i = blockIdx.x * blockDim.x + threadIdx.x;
    if (i >= RR * EE) return;
    int r = i / EE;
    atomicAdd(&rs_out[r * NN + src[i]], 1.0f);
    atomicAdd(&rs_in [r * NN + dst[i]], 1.0f);
}

__global__ void degree_finalize_kernel(float* p, int n) {
    int i = blockIdx.x * blockDim.x + threadIdx.x;
    if (i < n) p[i] = rsqrtf(fmaxf(p[i], 1.0f));
}

// acc[0:NN*F) = broadcast rows of (sum_r b[r][:]) -- vectorized float4
template <int F>
__global__ void init_bias_kernel(float* __restrict__ acc, const float* __restrict__ b) {
    int i = blockIdx.x * blockDim.x + threadIdx.x;   // float4 index
    if (i >= NN * F / 4) return;
    int f4 = i % (F / 4);
    const float4* b4 = reinterpret_cast<const float4*>(b);
    float4 v0 = __ldg(&b4[0 * (F / 4) + f4]);
    float4 v1 = __ldg(&b4[1 * (F / 4) + f4]);
    float4 v2 = __ldg(&b4[2 * (F / 4) + f4]);
    float4 v3 = __ldg(&b4[3 * (F / 4) + f4]);
    float4 s = make_float4(v0.x + v1.x + v2.x + v3.x,
                           v0.y + v1.y + v2.y + v3.y,
                           v0.z + v1.z + v2.z + v3.z,
                           v0.w + v1.w + v2.w + v3.w);
    reinterpret_cast<float4*>(acc)[i] = s;
}

// Split fp32 -> (hi, lo) bf16 pair, optional fused ReLU. n % 4 == 0.
template <bool RELU>
__global__ void split_kernel(const float* __restrict__ in,
                             __nv_bfloat16* __restrict__ hi,
                             __nv_bfloat16* __restrict__ lo, int n) {
    int i4 = (blockIdx.x * blockDim.x + threadIdx.x) * 4;
    if (i4 >= n) return;
    float4 v = *reinterpret_cast<const float4*>(in + i4);
    if (RELU) {
        v.x = fmaxf(v.x, 0.f); v.y = fmaxf(v.y, 0.f);
        v.z = fmaxf(v.z, 0.f); v.w = fmaxf(v.w, 0.f);
    }
    __nv_bfloat16 hx = __float2bfloat16(v.x), hy = __float2bfloat16(v.y);
    __nv_bfloat16 hz = __float2bfloat16(v.z), hw = __float2bfloat16(v.w);
    float lx = v.x - __bfloat162float(hx), ly = v.y - __bfloat162float(hy);
    float lz = v.z - __bfloat162float(hz), lw = v.w - __bfloat162float(hw);
    __nv_bfloat162* H = reinterpret_cast<__nv_bfloat162*>(hi + i4);
    __nv_bfloat162* L = reinterpret_cast<__nv_bfloat162*>(lo + i4);
    H[0] = __halves2bfloat162(hx, hy);
    H[1] = __halves2bfloat162(hz, hw);
    L[0] = __halves2bfloat162(__float2bfloat16(lx), __float2bfloat16(ly));
    L[1] = __halves2bfloat162(__float2bfloat16(lz), __float2bfloat16(lw));
}

// ---------------------------------------------------------------------------
// Tensor-core GEMM (3-term bf16 split), single relation:
//   Y[m, 0:BN] = rs_out[m] * (A[m, :] @ W[:, 0:BN])
// BM=128, BK=32, 256 threads (8 warps: 4 m x 2 n), warp tile 32 x BN/2.
// ---------------------------------------------------------------------------
template <int BN>
__global__ __launch_bounds__(256)
void gemm_bf16_kernel(const __nv_bfloat16* __restrict__ Ahi,
                      const __nv_bfloat16* __restrict__ Alo,
                      const __nv_bfloat16* __restrict__ Whi,
                      const __nv_bfloat16* __restrict__ Wlo,
                      const float* __restrict__ rs_out,
                      float* __restrict__ Y,
                      int M, int K) {
    constexpr int BM = 128;
    constexpr int BK = 32;
    constexpr int NT = BN / 16;       // n-tiles (8 cols each) per warp
    constexpr int AS = BK + 8;        // smem strides (bank-conflict-free for ldmatrix)
    constexpr int BS = BN + 8;

    __shared__ __align__(16) __nv_bfloat16 sAh[BM * AS], sAl[BM * AS];
    __shared__ __align__(16) __nv_bfloat16 sBh[BK * BS], sBl[BK * BS];

    const int t = threadIdx.x;
    const int lane = t & 31;
    const int wid = t >> 5;
    const int wm = wid & 3;           // warp row (32 rows each)
    const int wn = wid >> 2;          // warp col (BN/2 cols each)
    const int rowBase = blockIdx.x * BM;

    float acc[2][NT][4];
#pragma unroll
    for (int mt = 0; mt < 2; ++mt)
#pragma unroll
        for (int nt = 0; nt < NT; ++nt)
#pragma unroll
            for (int j = 0; j < 4; ++j) acc[mt][nt][j] = 0.f;

    for (int k0 = 0; k0 < K; k0 += BK) {
        // ---- A tiles (hi & lo): 128 rows x 32 cols
#pragma unroll
        for (int i = 0; i < 2; ++i) {
            int id = t + i * 256;
            int row = id >> 2;
            int c8 = (id & 3) * 8;
            int gr = rowBase + row;
            uint4 vh = make_uint4(0, 0, 0, 0), vl = make_uint4(0, 0, 0, 0);
            if (gr < M) {
                vh = *reinterpret_cast<const uint4*>(Ahi + (size_t)gr * K + k0 + c8);
                vl = *reinterpret_cast<const uint4*>(Alo + (size_t)gr * K + k0 + c8);
            }
            *reinterpret_cast<uint4*>(&sAh[row * AS + c8]) = vh;
            *reinterpret_cast<uint4*>(&sAl[row * AS + c8]) = vl;
        }
        // ---- B tiles (hi & lo): 32 rows x BN cols
#pragma unroll
        for (int i = 0; i < (BK * BN / 8) / 256; ++i) {
            int id = t + i * 256;
            int row = id / (BN / 8);
            int c8 = (id % (BN / 8)) * 8;
            *reinterpret_cast<uint4*>(&sBh[row * BS + c8]) =
                *reinterpret_cast<const uint4*>(Whi + (size_t)(k0 + row) * BN + c8);
            *reinterpret_cast<uint4*>(&sBl[row * BS + c8]) =
                *reinterpret_cast<const uint4*>(Wlo + (size_t)(k0 + row) * BN + c8);
        }
        __syncthreads();

#pragma unroll
        for (int kk = 0; kk < BK; kk += 16) {
            uint32_t ah[2][4], al[2][4];
#pragma unroll
            for (int mt = 0; mt < 2; ++mt) {
                int row = wm * 32 + mt * 16 + (lane & 15);
                int col = kk + (lane >> 4) * 8;
                ldsm_x4(ah[mt], (uint32_t)__cvta_generic_to_shared(&sAh[row * AS + col]));
                ldsm_x4(al[mt], (uint32_t)__cvta_generic_to_shared(&sAl[row * AS + col]));
            }
            uint32_t bh[NT][2], bl[NT][2];
#pragma unroll
            for (int nt = 0; nt < NT; ++nt) {
                int col = wn * (BN / 2) + nt * 8;
                int row = kk + (lane & 15);
                ldsm_x2t(bh[nt], (uint32_t)__cvta_generic_to_shared(&sBh[row * BS + col]));
                ldsm_x2t(bl[nt], (uint32_t)__cvta_generic_to_shared(&sBl[row * BS + col]));
            }
#pragma unroll
            for (int mt = 0; mt < 2; ++mt)
#pragma unroll
                for (int nt = 0; nt < NT; ++nt) {
                    mma16816(acc[mt][nt], ah[mt], bh[nt]);   // hi*hi
                    mma16816(acc[mt][nt], al[mt], bh[nt]);   // lo*hi
                    mma16816(acc[mt][nt], ah[mt], bl[nt]);   // hi*lo
                }
        }
        __syncthreads();
    }

    // ---- epilogue (rs_out row-scale folded in)
#pragma unroll
    for (int mt = 0; mt < 2; ++mt) {
        int gr0 = rowBase + wm * 32 + mt * 16 + (lane >> 2);
        int gc0 = wn * (BN / 2) + (lane & 3) * 2;
        float s0 = (gr0 < M)     ? __ldg(&rs_out[gr0])     : 0.f;
        float s1 = (gr0 + 8 < M) ? __ldg(&rs_out[gr0 + 8]) : 0.f;
#pragma unroll
        for (int nt = 0; nt < NT; ++nt) {
            int c = gc0 + nt * 8;
            if (gr0 < M)
                *reinterpret_cast<float2*>(Y + (size_t)gr0 * BN + c) =
                    make_float2(s0 * acc[mt][nt][0], s0 * acc[mt][nt][1]);
            if (gr0 + 8 < M)
                *reinterpret_cast<float2*>(Y + (size_t)(gr0 + 8) * BN + c) =
                    make_float2(s1 * acc[mt][nt][2], s1 * acc[mt][nt][3]);
        }
    }
}

// ---------------------------------------------------------------------------
// Edge scatter, single relation (Y_r L2-hot from preceding GEMM):
//   acc[d] += rs_in_r[d] * Y_r[s, :]          (rs_out already folded into Y)
// ---------------------------------------------------------------------------
__global__ __launch_bounds__(256)
void scatter_f128_kernel(const float* __restrict__ Y,
                         const int* __restrict__ esrc,
                         const int* __restrict__ edst,
                         const float* __restrict__ rs_in,
                         float* __restrict__ acc) {
    int gw = (blockIdx.x * blockDim.x + threadIdx.x) >> 5;
    int lane = threadIdx.x & 31;
    if (gw >= EE) return;
    int s = esrc[gw];
    int d = edst[gw];
    float c = __ldg(&rs_in[d]);
    float4 v = *reinterpret_cast<const float4*>(Y + (size_t)s * HIDF + lane * 4);
    float* p = acc + (size_t)d * HIDF + lane * 4;
    asm volatile("red.global.add.v4.f32 [%0], {%1,%2,%3,%4};"
                 :: "l"(p), "f"(c * v.x), "f"(c * v.y), "f"(c * v.z), "f"(c * v.w)
                 : "memory");
}

__global__ __launch_bounds__(256)
void scatter_f64_kernel(const float* __restrict__ Y,
                        const int* __restrict__ esrc,
                        const int* __restrict__ edst,
                        const float* __restrict__ rs_in,
                        float* __restrict__ acc) {
    int gw = (blockIdx.x * blockDim.x + threadIdx.x) >> 5;
    int lane = threadIdx.x & 31;
    if (gw >= EE) return;
    int s = esrc[gw];
    int d = edst[gw];
    float c = __ldg(&rs_in[d]);
    float2 v = *reinterpret_cast<const float2*>(Y + (size_t)s * OUTF + lane * 2);
    float* p = acc + (size_t)d * OUTF + lane * 2;
    asm volatile("red.global.add.v2.f32 [%0], {%1,%2};"
                 :: "l"(p), "f"(c * v.x), "f"(c * v.y)
                 : "memory");
}

// ---------------------------------------------------------------------------
// Launch
// ---------------------------------------------------------------------------
extern "C" void kernel_launch(void* const* d_in, const int* in_sizes, int n_in,
                              void* d_out, int out_size) {
    const float* x    = (const float*)d_in[0];
    const int*   esrc = (const int*)  d_in[1];
    const int*   edst = (const int*)  d_in[2];
    const float* W1   = (const float*)d_in[3];
    const float* b1   = (const float*)d_in[4];
    const float* W2   = (const float*)d_in[5];
    const float* b2   = (const float*)d_in[6];
    float* out = (float*)d_out;

    __nv_bfloat16 *xhi, *xlo, *w1hi, *w1lo, *w2hi, *w2lo, *a2hi, *a2lo;
    float *Y1, *Y2, *acc1, *rs;
    cudaGetSymbolAddress((void**)&xhi,  g_xhi);
    cudaGetSymbolAddress((void**)&xlo,  g_xlo);
    cudaGetSymbolAddress((void**)&w1hi, g_w1hi);
    cudaGetSymbolAddress((void**)&w1lo, g_w1lo);
    cudaGetSymbolAddress((void**)&w2hi, g_w2hi);
    cudaGetSymbolAddress((void**)&w2lo, g_w2lo);
    cudaGetSymbolAddress((void**)&a2hi, g_a2hi);
    cudaGetSymbolAddress((void**)&a2lo, g_a2lo);
    cudaGetSymbolAddress((void**)&Y1,   g_Y1);
    cudaGetSymbolAddress((void**)&Y2,   g_Y2);
    cudaGetSymbolAddress((void**)&acc1, g_acc1);
    cudaGetSymbolAddress((void**)&rs,   g_rs);
    float* rs_out = rs;
    float* rs_in  = rs + RR * NN;

    const int TPB = 256;

    // ---- degrees ----
    {
        int n = 2 * RR * NN;
        fzero_kernel<<<(n + TPB - 1) / TPB, TPB>>>(rs, n);
        degree_count_kernel<<<(RR * EE + TPB - 1) / TPB, TPB>>>(esrc, edst, rs_out, rs_in);
        degree_finalize_kernel<<<(n + TPB - 1) / TPB, TPB>>>(rs, n);
    }

    // ---- bf16 splits of inputs/weights ----
    {
        int nx = NN * INF;
        split_kernel<false><<<(nx / 4 + TPB - 1) / TPB, TPB>>>(x, xhi, xlo, nx);
        int nw1 = RR * INF * HIDF;
        split_kernel<false><<<(nw1 / 4 + TPB - 1) / TPB, TPB>>>(W1, w1hi, w1lo, nw1);
        int nw2 = RR * HIDF * OUTF;
        split_kernel<false><<<(nw2 / 4 + TPB - 1) / TPB, TPB>>>(W2, w2hi, w2lo, nw2);
    }

    const int gemmGrid    = (NN + 127) / 128;              // 782
    const int scatterGrid = (EE * 32 + TPB - 1) / TPB;     // 62500

    // ---- Layer 1: per relation GEMM -> scatter (Y_r stays L2-hot) ----
    init_bias_kernel<HIDF><<<(NN * HIDF / 4 + TPB - 1) / TPB, TPB>>>(acc1, b1);
    for (int r = 0; r < RR; ++r) {
        gemm_bf16_kernel<HIDF><<<gemmGrid, TPB>>>(
            xhi, xlo,
            w1hi + (size_t)r * INF * HIDF, w1lo + (size_t)r * INF * HIDF,
            rs_out + r * NN,
            Y1 + (size_t)r * NN * HIDF, NN, INF);
        scatter_f128_kernel<<<scatterGrid, TPB>>>(
            Y1 + (size_t)r * NN * HIDF,
            esrc + (size_t)r * EE, edst + (size_t)r * EE,
            rs_in + r * NN, acc1);
    }

    // ---- ReLU + split for layer 2 ----
    {
        int n = NN * HIDF;
        split_kernel<true><<<(n / 4 + TPB - 1) / TPB, TPB>>>(acc1, a2hi, a2lo, n);
    }

    // ---- Layer 2: per relation GEMM -> scatter ----
    init_bias_kernel<OUTF><<<(NN * OUTF / 4 + TPB - 1) / TPB, TPB>>>(out, b2);
    for (int r = 0; r < RR; ++r) {
        gemm_bf16_kernel<OUTF><<<gemmGrid, TPB>>>(
            a2hi, a2lo,
            w2hi + (size_t)r * HIDF * OUTF, w2lo + (size_t)r * HIDF * OUTF,
            rs_out + r * NN,
            Y2 + (size_t)r * NN * OUTF, NN, HIDF);
        scatter_f64_kernel<<<scatterGrid, TPB>>>(
            Y2 + (size_t)r * NN * OUTF,
            esrc + (size_t)r * EE, edst + (size_t)r * EE,
            rs_in + r * NN, out);
    }
}

// round 8
// speedup vs baseline: 1.0404x; 1.0404x over previous
#include <cuda_runtime.h>
#include <cuda_bf16.h>
#include <cstdint>

// Problem constants
#define NN   100000   // nodes
#define RR   4        // relations
#define EE   500000   // edges per relation
#define INF  256
#define HIDF 128
#define OUTF 64

// ---------------------------------------------------------------------------
// Static device scratch (allocation-free per harness rules)
// ---------------------------------------------------------------------------
static __device__ __nv_bfloat16 g_xhi[(size_t)NN * INF];     // 51.2 MB
static __device__ __nv_bfloat16 g_xlo[(size_t)NN * INF];     // 51.2 MB
static __device__ __nv_bfloat16 g_w1hi[RR * INF * HIDF];
static __device__ __nv_bfloat16 g_w1lo[RR * INF * HIDF];
static __device__ __nv_bfloat16 g_w2hi[RR * HIDF * OUTF];
static __device__ __nv_bfloat16 g_w2lo[RR * HIDF * OUTF];
static __device__ __nv_bfloat16 g_a2hi[(size_t)NN * HIDF];   // 25.6 MB
static __device__ __nv_bfloat16 g_a2lo[(size_t)NN * HIDF];   // 25.6 MB
static __device__ float g_Y1[(size_t)RR * NN * HIDF];        // 204.8 MB  [r][n][128]
static __device__ float g_Y2[(size_t)RR * NN * OUTF];        // 102.4 MB  [r][n][64]
static __device__ float g_acc1[(size_t)NN * HIDF];           // 51.2 MB
static __device__ int   g_cnt_out[RR * NN];
static __device__ int   g_cnt_in[RR * NN];
static __device__ float g_rs_out[RR * NN];
static __device__ float g_rs_in[RR * NN];
static __device__ int   g_offs[RR * NN];                     // src-CSR segment starts
static __device__ int   g_cur[RR * NN];                      // fill cursors
static __device__ int   g_relctr[RR];                        // per-relation bump allocators
static __device__ int2  g_csr[(size_t)RR * EE];              // (dst, bits(rs_in_r[dst]))

// ---------------------------------------------------------------------------
// Tensor-core primitives (mma.sync bf16 -> f32)
// ---------------------------------------------------------------------------
__device__ __forceinline__ void ldsm_x4(uint32_t* r, uint32_t a) {
    asm volatile("ldmatrix.sync.aligned.m8n8.x4.shared.b16 {%0,%1,%2,%3}, [%4];"
                 : "=r"(r[0]), "=r"(r[1]), "=r"(r[2]), "=r"(r[3]) : "r"(a));
}
__device__ __forceinline__ void ldsm_x2t(uint32_t* r, uint32_t a) {
    asm volatile("ldmatrix.sync.aligned.m8n8.x2.trans.shared.b16 {%0,%1}, [%2];"
                 : "=r"(r[0]), "=r"(r[1]) : "r"(a));
}
__device__ __forceinline__ void mma16816(float* c, const uint32_t* a, const uint32_t* b) {
    asm volatile(
        "mma.sync.aligned.m16n8k16.row.col.f32.bf16.bf16.f32 "
        "{%0,%1,%2,%3}, {%4,%5,%6,%7}, {%8,%9}, {%0,%1,%2,%3};"
        : "+f"(c[0]), "+f"(c[1]), "+f"(c[2]), "+f"(c[3])
        : "r"(a[0]), "r"(a[1]), "r"(a[2]), "r"(a[3]), "r"(b[0]), "r"(b[1]));
}

// ---------------------------------------------------------------------------
// Preprocessing kernels
// ---------------------------------------------------------------------------
__global__ void degree_count_kernel(const int* __restrict__ src,
                                    const int* __restrict__ dst,
                                    int* __restrict__ cnt_out,
                                    int* __restrict__ cnt_in) {
    int i = blockIdx.x * blockDim.x + threadIdx.x;
    if (i >= RR * EE) return;
    int r = i / EE;
    atomicAdd(&cnt_out[r * NN + src[i]], 1);
    atomicAdd(&cnt_in [r * NN + dst[i]], 1);
}

__global__ void rs_kernel(const int* __restrict__ cnt_out,
                          const int* __restrict__ cnt_in,
                          float* __restrict__ rs_out,
                          float* __restrict__ rs_in) {
    int i = blockIdx.x * blockDim.x + threadIdx.x;
    if (i >= RR * NN) return;
    rs_out[i] = rsqrtf((float)max(cnt_out[i], 1));
    rs_in [i] = rsqrtf((float)max(cnt_in [i], 1));
}

// Bump-allocate contiguous per-(relation,src) segments (order irrelevant).
__global__ void alloc_offsets_kernel(const int* __restrict__ cnt_out,
                                     int* __restrict__ offs,
                                     int* __restrict__ cur,
                                     int* __restrict__ relctr) {
    int i = blockIdx.x * blockDim.x + threadIdx.x;
    if (i >= RR * NN) return;
    int r = i / NN;
    int off = atomicAdd(&relctr[r], cnt_out[i]);
    offs[i] = off;
    cur[i]  = off;
}

__global__ void csr_fill_kernel(const int* __restrict__ src,
                                const int* __restrict__ dst,
                                const float* __restrict__ rs_in,
                                int* __restrict__ cur,
                                int2* __restrict__ csr) {
    int i = blockIdx.x * blockDim.x + threadIdx.x;
    if (i >= RR * EE) return;
    int r = i / EE;
    int s = src[i];
    int d = dst[i];
    int pos = atomicAdd(&cur[r * NN + s], 1);
    csr[(size_t)r * EE + pos] = make_int2(d, __float_as_int(__ldg(&rs_in[r * NN + d])));
}

// acc[0:NN*F) = rows of (sum_r b[r][:]) -- vectorized float4
template <int F>
__global__ void init_bias_kernel(float* __restrict__ acc, const float* __restrict__ b) {
    int i = blockIdx.x * blockDim.x + threadIdx.x;   // float4 index
    if (i >= NN * F / 4) return;
    int f4 = i % (F / 4);
    const float4* b4 = reinterpret_cast<const float4*>(b);
    float4 v0 = __ldg(&b4[0 * (F / 4) + f4]);
    float4 v1 = __ldg(&b4[1 * (F / 4) + f4]);
    float4 v2 = __ldg(&b4[2 * (F / 4) + f4]);
    float4 v3 = __ldg(&b4[3 * (F / 4) + f4]);
    reinterpret_cast<float4*>(acc)[i] =
        make_float4(v0.x + v1.x + v2.x + v3.x, v0.y + v1.y + v2.y + v3.y,
                    v0.z + v1.z + v2.z + v3.z, v0.w + v1.w + v2.w + v3.w);
}

// Split fp32 -> (hi, lo) bf16 pair, optional fused ReLU. n % 4 == 0.
template <bool RELU>
__global__ void split_kernel(const float* __restrict__ in,
                             __nv_bfloat16* __restrict__ hi,
                             __nv_bfloat16* __restrict__ lo, int n) {
    int i4 = (blockIdx.x * blockDim.x + threadIdx.x) * 4;
    if (i4 >= n) return;
    float4 v = *reinterpret_cast<const float4*>(in + i4);
    if (RELU) {
        v.x = fmaxf(v.x, 0.f); v.y = fmaxf(v.y, 0.f);
        v.z = fmaxf(v.z, 0.f); v.w = fmaxf(v.w, 0.f);
    }
    __nv_bfloat16 hx = __float2bfloat16(v.x), hy = __float2bfloat16(v.y);
    __nv_bfloat16 hz = __float2bfloat16(v.z), hw = __float2bfloat16(v.w);
    float lx = v.x - __bfloat162float(hx), ly = v.y - __bfloat162float(hy);
    float lz = v.z - __bfloat162float(hz), lw = v.w - __bfloat162float(hw);
    __nv_bfloat162* H = reinterpret_cast<__nv_bfloat162*>(hi + i4);
    __nv_bfloat162* L = reinterpret_cast<__nv_bfloat162*>(lo + i4);
    H[0] = __halves2bfloat162(hx, hy);
    H[1] = __halves2bfloat162(hz, hw);
    L[0] = __halves2bfloat162(__float2bfloat16(lx), __float2bfloat16(ly));
    L[1] = __halves2bfloat162(__float2bfloat16(lz), __float2bfloat16(lw));
}

// ---------------------------------------------------------------------------
// Tensor-core GEMM (3-term bf16 split), batched over relations (blockIdx.y):
//   Y[r][m, 0:BN] = rs_out_r[m] * (A[m, :] @ W_r[:, 0:BN])
// ---------------------------------------------------------------------------
template <int BN>
__global__ __launch_bounds__(256)
void gemm_bf16_kernel(const __nv_bfloat16* __restrict__ Ahi,
                      const __nv_bfloat16* __restrict__ Alo,
                      const __nv_bfloat16* __restrict__ Whi,
                      const __nv_bfloat16* __restrict__ Wlo,
                      const float* __restrict__ rs_out,
                      float* __restrict__ Y,
                      int M, int K) {
    constexpr int BM = 128;
    constexpr int BK = 32;
    constexpr int NT = BN / 16;
    constexpr int AS = BK + 8;
    constexpr int BS = BN + 8;

    __shared__ __align__(16) __nv_bfloat16 sAh[BM * AS], sAl[BM * AS];
    __shared__ __align__(16) __nv_bfloat16 sBh[BK * BS], sBl[BK * BS];

    const int t = threadIdx.x;
    const int lane = t & 31;
    const int wid = t >> 5;
    const int wm = wid & 3;
    const int wn = wid >> 2;
    const int rowBase = blockIdx.x * BM;
    const int rel = blockIdx.y;

    const __nv_bfloat16* WhiR = Whi + (size_t)rel * K * BN;
    const __nv_bfloat16* WloR = Wlo + (size_t)rel * K * BN;
    const float* rsR = rs_out + rel * NN;
    float* YR = Y + (size_t)rel * NN * BN;

    float acc[2][NT][4];
#pragma unroll
    for (int mt = 0; mt < 2; ++mt)
#pragma unroll
        for (int nt = 0; nt < NT; ++nt)
#pragma unroll
            for (int j = 0; j < 4; ++j) acc[mt][nt][j] = 0.f;

    for (int k0 = 0; k0 < K; k0 += BK) {
#pragma unroll
        for (int i = 0; i < 2; ++i) {
            int id = t + i * 256;
            int row = id >> 2;
            int c8 = (id & 3) * 8;
            int gr = rowBase + row;
            uint4 vh = make_uint4(0, 0, 0, 0), vl = make_uint4(0, 0, 0, 0);
            if (gr < M) {
                vh = *reinterpret_cast<const uint4*>(Ahi + (size_t)gr * K + k0 + c8);
                vl = *reinterpret_cast<const uint4*>(Alo + (size_t)gr * K + k0 + c8);
            }
            *reinterpret_cast<uint4*>(&sAh[row * AS + c8]) = vh;
            *reinterpret_cast<uint4*>(&sAl[row * AS + c8]) = vl;
        }
#pragma unroll
        for (int i = 0; i < (BK * BN / 8) / 256; ++i) {
            int id = t + i * 256;
            int row = id / (BN / 8);
            int c8 = (id % (BN / 8)) * 8;
            *reinterpret_cast<uint4*>(&sBh[row * BS + c8]) =
                *reinterpret_cast<const uint4*>(WhiR + (size_t)(k0 + row) * BN + c8);
            *reinterpret_cast<uint4*>(&sBl[row * BS + c8]) =
                *reinterpret_cast<const uint4*>(WloR + (size_t)(k0 + row) * BN + c8);
        }
        __syncthreads();

#pragma unroll
        for (int kk = 0; kk < BK; kk += 16) {
            uint32_t ah[2][4], al[2][4];
#pragma unroll
            for (int mt = 0; mt < 2; ++mt) {
                int row = wm * 32 + mt * 16 + (lane & 15);
                int col = kk + (lane >> 4) * 8;
                ldsm_x4(ah[mt], (uint32_t)__cvta_generic_to_shared(&sAh[row * AS + col]));
                ldsm_x4(al[mt], (uint32_t)__cvta_generic_to_shared(&sAl[row * AS + col]));
            }
            uint32_t bh[NT][2], bl[NT][2];
#pragma unroll
            for (int nt = 0; nt < NT; ++nt) {
                int col = wn * (BN / 2) + nt * 8;
                int row = kk + (lane & 15);
                ldsm_x2t(bh[nt], (uint32_t)__cvta_generic_to_shared(&sBh[row * BS + col]));
                ldsm_x2t(bl[nt], (uint32_t)__cvta_generic_to_shared(&sBl[row * BS + col]));
            }
#pragma unroll
            for (int mt = 0; mt < 2; ++mt)
#pragma unroll
                for (int nt = 0; nt < NT; ++nt) {
                    mma16816(acc[mt][nt], ah[mt], bh[nt]);
                    mma16816(acc[mt][nt], al[mt], bh[nt]);
                    mma16816(acc[mt][nt], ah[mt], bl[nt]);
                }
        }
        __syncthreads();
    }

#pragma unroll
    for (int mt = 0; mt < 2; ++mt) {
        int gr0 = rowBase + wm * 32 + mt * 16 + (lane >> 2);
        int gc0 = wn * (BN / 2) + (lane & 3) * 2;
        float s0 = (gr0 < M)     ? __ldg(&rsR[gr0])     : 0.f;
        float s1 = (gr0 + 8 < M) ? __ldg(&rsR[gr0 + 8]) : 0.f;
#pragma unroll
        for (int nt = 0; nt < NT; ++nt) {
            int c = gc0 + nt * 8;
            if (gr0 < M)
                *reinterpret_cast<float2*>(YR + (size_t)gr0 * BN + c) =
                    make_float2(s0 * acc[mt][nt][0], s0 * acc[mt][nt][1]);
            if (gr0 + 8 < M)
                *reinterpret_cast<float2*>(YR + (size_t)(gr0 + 8) * BN + c) =
                    make_float2(s1 * acc[mt][nt][2], s1 * acc[mt][nt][3]);
        }
    }
}

// ---------------------------------------------------------------------------
// Src-ordered scatter: warp per (relation, src). Load Y row ONCE into
// registers, then one vector-RED per out-edge. All relations in one launch.
//   acc[d] += rs_in_r[d] * Y[r][s, :]      (rs_out folded into Y)
// ---------------------------------------------------------------------------
__global__ __launch_bounds__(256)
void scatter_src_f128_kernel(const float* __restrict__ Y,
                             const int2* __restrict__ csr,
                             const int* __restrict__ offs,
                             const int* __restrict__ cnt,
                             float* __restrict__ acc) {
    int gs = (blockIdx.x * blockDim.x + threadIdx.x) >> 5;   // r*NN + s
    if (gs >= RR * NN) return;
    int n = cnt[gs];
    if (n == 0) return;
    int lane = threadIdx.x & 31;
    int r = gs / NN;
    const int2* ep = csr + (size_t)r * EE + offs[gs];
    float4 v = *reinterpret_cast<const float4*>(Y + (size_t)gs * HIDF + lane * 4);
    for (int e = 0; e < n; ++e) {
        int2 ew = __ldg(ep + e);                 // broadcast across lanes
        float c = __int_as_float(ew.y);
        float* p = acc + (size_t)ew.x * HIDF + lane * 4;
        asm volatile("red.global.add.v4.f32 [%0], {%1,%2,%3,%4};"
                     :: "l"(p), "f"(c * v.x), "f"(c * v.y), "f"(c * v.z), "f"(c * v.w)
                     : "memory");
    }
}

__global__ __launch_bounds__(256)
void scatter_src_f64_kernel(const float* __restrict__ Y,
                            const int2* __restrict__ csr,
                            const int* __restrict__ offs,
                            const int* __restrict__ cnt,
                            float* __restrict__ acc) {
    int gs = (blockIdx.x * blockDim.x + threadIdx.x) >> 5;
    if (gs >= RR * NN) return;
    int n = cnt[gs];
    if (n == 0) return;
    int lane = threadIdx.x & 31;
    int r = gs / NN;
    const int2* ep = csr + (size_t)r * EE + offs[gs];
    float2 v = *reinterpret_cast<const float2*>(Y + (size_t)gs * OUTF + lane * 2);
    for (int e = 0; e < n; ++e) {
        int2 ew = __ldg(ep + e);
        float c = __int_as_float(ew.y);
        float* p = acc + (size_t)ew.x * OUTF + lane * 2;
        asm volatile("red.global.add.v2.f32 [%0], {%1,%2};"
                     :: "l"(p), "f"(c * v.x), "f"(c * v.y)
                     : "memory");
    }
}

// ---------------------------------------------------------------------------
// Launch
// ---------------------------------------------------------------------------
extern "C" void kernel_launch(void* const* d_in, const int* in_sizes, int n_in,
                              void* d_out, int out_size) {
    const float* x    = (const float*)d_in[0];
    const int*   esrc = (const int*)  d_in[1];
    const int*   edst = (const int*)  d_in[2];
    const float* W1   = (const float*)d_in[3];
    const float* b1   = (const float*)d_in[4];
    const float* W2   = (const float*)d_in[5];
    const float* b2   = (const float*)d_in[6];
    float* out = (float*)d_out;

    __nv_bfloat16 *xhi, *xlo, *w1hi, *w1lo, *w2hi, *w2lo, *a2hi, *a2lo;
    float *Y1, *Y2, *acc1, *rs_out, *rs_in;
    int *cnt_out, *cnt_in, *offs, *cur, *relctr;
    int2* csr;
    cudaGetSymbolAddress((void**)&xhi,     g_xhi);
    cudaGetSymbolAddress((void**)&xlo,     g_xlo);
    cudaGetSymbolAddress((void**)&w1hi,    g_w1hi);
    cudaGetSymbolAddress((void**)&w1lo,    g_w1lo);
    cudaGetSymbolAddress((void**)&w2hi,    g_w2hi);
    cudaGetSymbolAddress((void**)&w2lo,    g_w2lo);
    cudaGetSymbolAddress((void**)&a2hi,    g_a2hi);
    cudaGetSymbolAddress((void**)&a2lo,    g_a2lo);
    cudaGetSymbolAddress((void**)&Y1,      g_Y1);
    cudaGetSymbolAddress((void**)&Y2,      g_Y2);
    cudaGetSymbolAddress((void**)&acc1,    g_acc1);
    cudaGetSymbolAddress((void**)&cnt_out, g_cnt_out);
    cudaGetSymbolAddress((void**)&cnt_in,  g_cnt_in);
    cudaGetSymbolAddress((void**)&rs_out,  g_rs_out);
    cudaGetSymbolAddress((void**)&rs_in,   g_rs_in);
    cudaGetSymbolAddress((void**)&offs,    g_offs);
    cudaGetSymbolAddress((void**)&cur,     g_cur);
    cudaGetSymbolAddress((void**)&relctr,  g_relctr);
    cudaGetSymbolAddress((void**)&csr,     g_csr);

    const int TPB = 256;

    // ---- degrees + src-CSR build ----
    cudaMemsetAsync(cnt_out, 0, RR * NN * sizeof(int));
    cudaMemsetAsync(cnt_in,  0, RR * NN * sizeof(int));
    cudaMemsetAsync(relctr,  0, RR * sizeof(int));
    degree_count_kernel<<<(RR * EE + TPB - 1) / TPB, TPB>>>(esrc, edst, cnt_out, cnt_in);
    rs_kernel<<<(RR * NN + TPB - 1) / TPB, TPB>>>(cnt_out, cnt_in, rs_out, rs_in);
    alloc_offsets_kernel<<<(RR * NN + TPB - 1) / TPB, TPB>>>(cnt_out, offs, cur, relctr);
    csr_fill_kernel<<<(RR * EE + TPB - 1) / TPB, TPB>>>(esrc, edst, rs_in, cur, csr);

    // ---- bf16 splits of inputs/weights ----
    {
        int nx = NN * INF;
        split_kernel<false><<<(nx / 4 + TPB - 1) / TPB, TPB>>>(x, xhi, xlo, nx);
        int nw1 = RR * INF * HIDF;
        split_kernel<false><<<(nw1 / 4 + TPB - 1) / TPB, TPB>>>(W1, w1hi, w1lo, nw1);
        int nw2 = RR * HIDF * OUTF;
        split_kernel<false><<<(nw2 / 4 + TPB - 1) / TPB, TPB>>>(W2, w2hi, w2lo, nw2);
    }

    const dim3 gemmGrid((NN + 127) / 128, RR);
    const int scatterGrid = (RR * NN * 32 + TPB - 1) / TPB;   // warp per (r, src)

    // ---- Layer 1 ----
    init_bias_kernel<HIDF><<<(NN * HIDF / 4 + TPB - 1) / TPB, TPB>>>(acc1, b1);
    gemm_bf16_kernel<HIDF><<<gemmGrid, TPB>>>(xhi, xlo, w1hi, w1lo, rs_out, Y1, NN, INF);
    scatter_src_f128_kernel<<<scatterGrid, TPB>>>(Y1, csr, offs, cnt_out, acc1);

    // ---- ReLU + split for layer 2 ----
    {
        int n = NN * HIDF;
        split_kernel<true><<<(n / 4 + TPB - 1) / TPB, TPB>>>(acc1, a2hi, a2lo, n);
    }

    // ---- Layer 2 ----
    init_bias_kernel<OUTF><<<(NN * OUTF / 4 + TPB - 1) / TPB, TPB>>>(out, b2);
    gemm_bf16_kernel<OUTF><<<gemmGrid, TPB>>>(a2hi, a2lo, w2hi, w2lo, rs_out, Y2, NN, HIDF);
    scatter_src_f64_kernel<<<scatterGrid, TPB>>>(Y2, csr, offs, cnt_out, out);
}

// round 10
// speedup vs baseline: 1.0903x; 1.0480x over previous
#include <cuda_runtime.h>
#include <cuda_bf16.h>
#include <cstdint>

// Problem constants
#define NN   100000   // nodes
#define RR   4        // relations
#define EE   500000   // edges per relation
#define INF  256
#define HIDF 128
#define OUTF 64

// ---------------------------------------------------------------------------
// Static device scratch (allocation-free per harness rules)
// ---------------------------------------------------------------------------
static __device__ __nv_bfloat16 g_xhi[(size_t)NN * INF];     // 51.2 MB
static __device__ __nv_bfloat16 g_xlo[(size_t)NN * INF];     // 51.2 MB
static __device__ __nv_bfloat16 g_w1hi[RR * INF * HIDF];
static __device__ __nv_bfloat16 g_w1lo[RR * INF * HIDF];
static __device__ __nv_bfloat16 g_w2hi[RR * HIDF * OUTF];
static __device__ __nv_bfloat16 g_w2lo[RR * HIDF * OUTF];
static __device__ __nv_bfloat16 g_a2hi[(size_t)NN * HIDF];   // 25.6 MB
static __device__ __nv_bfloat16 g_a2lo[(size_t)NN * HIDF];   // 25.6 MB
static __device__ float g_Y1[(size_t)RR * NN * HIDF];        // 204.8 MB  [r][n][128]
static __device__ float g_Y2[(size_t)RR * NN * OUTF];        // 102.4 MB  [r][n][64]
static __device__ float g_acc1[(size_t)NN * HIDF];           // 51.2 MB
static __device__ int   g_cnt_out[RR * NN];
static __device__ int   g_cnt_in[RR * NN];
static __device__ float g_rs_out[RR * NN];
static __device__ float g_rs_in[RR * NN];

// ---------------------------------------------------------------------------
// Tensor-core / async-copy primitives
// ---------------------------------------------------------------------------
__device__ __forceinline__ void ldsm_x4(uint32_t* r, uint32_t a) {
    asm volatile("ldmatrix.sync.aligned.m8n8.x4.shared.b16 {%0,%1,%2,%3}, [%4];"
                 : "=r"(r[0]), "=r"(r[1]), "=r"(r[2]), "=r"(r[3]) : "r"(a));
}
__device__ __forceinline__ void ldsm_x2t(uint32_t* r, uint32_t a) {
    asm volatile("ldmatrix.sync.aligned.m8n8.x2.trans.shared.b16 {%0,%1}, [%2];"
                 : "=r"(r[0]), "=r"(r[1]) : "r"(a));
}
__device__ __forceinline__ void mma16816(float* c, const uint32_t* a, const uint32_t* b) {
    asm volatile(
        "mma.sync.aligned.m16n8k16.row.col.f32.bf16.bf16.f32 "
        "{%0,%1,%2,%3}, {%4,%5,%6,%7}, {%8,%9}, {%0,%1,%2,%3};"
        : "+f"(c[0]), "+f"(c[1]), "+f"(c[2]), "+f"(c[3])
        : "r"(a[0]), "r"(a[1]), "r"(a[2]), "r"(a[3]), "r"(b[0]), "r"(b[1]));
}
// 16-byte async copy; pred=false -> zero-fill destination.
__device__ __forceinline__ void cp_async16(void* smem, const void* gmem, bool pred) {
    uint32_t s = (uint32_t)__cvta_generic_to_shared(smem);
    int sz = pred ? 16 : 0;
    asm volatile("cp.async.cg.shared.global [%0], [%1], 16, %2;"
                 :: "r"(s), "l"(gmem), "r"(sz));
}
__device__ __forceinline__ void cp_commit() {
    asm volatile("cp.async.commit_group;");
}
template <int N>
__device__ __forceinline__ void cp_wait() {
    asm volatile("cp.async.wait_group %0;" :: "n"(N));
}

// ---------------------------------------------------------------------------
// Preprocessing kernels
// ---------------------------------------------------------------------------
__global__ void degree_count_kernel(const int* __restrict__ src,
                                    const int* __restrict__ dst,
                                    int* __restrict__ cnt_out,
                                    int* __restrict__ cnt_in) {
    int i = blockIdx.x * blockDim.x + threadIdx.x;
    if (i >= RR * EE) return;
    int r = i / EE;
    atomicAdd(&cnt_out[r * NN + src[i]], 1);
    atomicAdd(&cnt_in [r * NN + dst[i]], 1);
}

__global__ void rs_kernel(const int* __restrict__ cnt_out,
                          const int* __restrict__ cnt_in,
                          float* __restrict__ rs_out,
                          float* __restrict__ rs_in) {
    int i = blockIdx.x * blockDim.x + threadIdx.x;
    if (i >= RR * NN) return;
    rs_out[i] = rsqrtf((float)max(cnt_out[i], 1));
    rs_in [i] = rsqrtf((float)max(cnt_in [i], 1));
}

// acc[0:NN*F) = rows of (sum_r b[r][:]) -- vectorized float4
template <int F>
__global__ void init_bias_kernel(float* __restrict__ acc, const float* __restrict__ b) {
    int i = blockIdx.x * blockDim.x + threadIdx.x;   // float4 index
    if (i >= NN * F / 4) return;
    int f4 = i % (F / 4);
    const float4* b4 = reinterpret_cast<const float4*>(b);
    float4 v0 = __ldg(&b4[0 * (F / 4) + f4]);
    float4 v1 = __ldg(&b4[1 * (F / 4) + f4]);
    float4 v2 = __ldg(&b4[2 * (F / 4) + f4]);
    float4 v3 = __ldg(&b4[3 * (F / 4) + f4]);
    reinterpret_cast<float4*>(acc)[i] =
        make_float4(v0.x + v1.x + v2.x + v3.x, v0.y + v1.y + v2.y + v3.y,
                    v0.z + v1.z + v2.z + v3.z, v0.w + v1.w + v2.w + v3.w);
}

// Split fp32 -> (hi, lo) bf16 pair, optional fused ReLU. n % 4 == 0.
template <bool RELU>
__global__ void split_kernel(const float* __restrict__ in,
                             __nv_bfloat16* __restrict__ hi,
                             __nv_bfloat16* __restrict__ lo, int n) {
    int i4 = (blockIdx.x * blockDim.x + threadIdx.x) * 4;
    if (i4 >= n) return;
    float4 v = *reinterpret_cast<const float4*>(in + i4);
    if (RELU) {
        v.x = fmaxf(v.x, 0.f); v.y = fmaxf(v.y, 0.f);
        v.z = fmaxf(v.z, 0.f); v.w = fmaxf(v.w, 0.f);
    }
    __nv_bfloat16 hx = __float2bfloat16(v.x), hy = __float2bfloat16(v.y);
    __nv_bfloat16 hz = __float2bfloat16(v.z), hw = __float2bfloat16(v.w);
    float lx = v.x - __bfloat162float(hx), ly = v.y - __bfloat162float(hy);
    float lz = v.z - __bfloat162float(hz), lw = v.w - __bfloat162float(hw);
    __nv_bfloat162* H = reinterpret_cast<__nv_bfloat162*>(hi + i4);
    __nv_bfloat162* L = reinterpret_cast<__nv_bfloat162*>(lo + i4);
    H[0] = __halves2bfloat162(hx, hy);
    H[1] = __halves2bfloat162(hz, hw);
    L[0] = __halves2bfloat162(__float2bfloat16(lx), __float2bfloat16(ly));
    L[1] = __halves2bfloat162(__float2bfloat16(lz), __float2bfloat16(lw));
}

// ---------------------------------------------------------------------------
// Pipelined tensor-core GEMM (3-term bf16 split), batched over relations:
//   Y[r][m, 0:BN] = rs_out_r[m] * (A[m, :] @ W_r[:, 0:BN])
// BM=128, BK=16, 2-stage cp.async double buffer, 256 threads (8 warps).
// ---------------------------------------------------------------------------
template <int BN>
__global__ __launch_bounds__(256)
void gemm_bf16_pipe_kernel(const __nv_bfloat16* __restrict__ Ahi,
                           const __nv_bfloat16* __restrict__ Alo,
                           const __nv_bfloat16* __restrict__ Whi,
                           const __nv_bfloat16* __restrict__ Wlo,
                           const float* __restrict__ rs_out,
                           float* __restrict__ Y,
                           int M, int K) {
    constexpr int BM = 128;
    constexpr int BK = 16;
    constexpr int NT = BN / 16;       // n-tiles (8 cols each) per warp
    constexpr int AS = BK + 8;        // 24 bf16 = 48B row stride (16B aligned)
    constexpr int BS = BN + 8;        // (BN+8) bf16 row stride (16B aligned)
    constexpr int BCH = 2 * BN;       // 16-byte chunks in one B tile (BK*BN/8)

    __shared__ __align__(16) __nv_bfloat16 sAh[2][BM * AS], sAl[2][BM * AS];
    __shared__ __align__(16) __nv_bfloat16 sBh[2][BK * BS], sBl[2][BK * BS];

    const int t = threadIdx.x;
    const int lane = t & 31;
    const int wid = t >> 5;
    const int wm = wid & 3;           // warp row (32 rows each)
    const int wn = wid >> 2;          // warp col (BN/2 cols each)
    const int rowBase = blockIdx.x * BM;
    const int rel = blockIdx.y;

    const __nv_bfloat16* WhiR = Whi + (size_t)rel * K * BN;
    const __nv_bfloat16* WloR = Wlo + (size_t)rel * K * BN;
    const float* rsR = rs_out + rel * NN;
    float* YR = Y + (size_t)rel * NN * BN;

    // per-thread load coordinates
    const int arow = t >> 1;                 // 0..127
    const int acol = (t & 1) * 8;            // 0 or 8 (bf16 units; 16B chunks)
    const int agr  = rowBase + arow;
    const bool apred = agr < M;
    const int brow = t / (BN / 8);           // B tile row (valid if t < BCH)
    const int bc8  = (t % (BN / 8)) * 8;

    float acc[2][NT][4];
#pragma unroll
    for (int mt = 0; mt < 2; ++mt)
#pragma unroll
        for (int nt = 0; nt < NT; ++nt)
#pragma unroll
            for (int j = 0; j < 4; ++j) acc[mt][nt][j] = 0.f;

    const int ntiles = K / BK;

    // ---- prologue: stage 0 loads
    {
        cp_async16(&sAh[0][arow * AS + acol], Ahi + (size_t)agr * K + acol, apred);
        cp_async16(&sAl[0][arow * AS + acol], Alo + (size_t)agr * K + acol, apred);
        if (t < BCH) {
            cp_async16(&sBh[0][brow * BS + bc8], WhiR + (size_t)brow * BN + bc8, true);
            cp_async16(&sBl[0][brow * BS + bc8], WloR + (size_t)brow * BN + bc8, true);
        }
        cp_commit();
    }

    for (int tt = 0; tt < ntiles; ++tt) {
        int st = tt & 1;
        if (tt + 1 < ntiles) {
            int ns = st ^ 1;
            int k0 = (tt + 1) * BK;
            cp_async16(&sAh[ns][arow * AS + acol], Ahi + (size_t)agr * K + k0 + acol, apred);
            cp_async16(&sAl[ns][arow * AS + acol], Alo + (size_t)agr * K + k0 + acol, apred);
            if (t < BCH) {
                cp_async16(&sBh[ns][brow * BS + bc8], WhiR + (size_t)(k0 + brow) * BN + bc8, true);
                cp_async16(&sBl[ns][brow * BS + bc8], WloR + (size_t)(k0 + brow) * BN + bc8, true);
            }
            cp_commit();
            cp_wait<1>();
        } else {
            cp_wait<0>();
        }
        __syncthreads();

        // ---- compute one BK=16 step
        uint32_t ah[2][4], al[2][4];
#pragma unroll
        for (int mt = 0; mt < 2; ++mt) {
            int row = wm * 32 + mt * 16 + (lane & 15);
            int col = (lane >> 4) * 8;
            ldsm_x4(ah[mt], (uint32_t)__cvta_generic_to_shared(&sAh[st][row * AS + col]));
            ldsm_x4(al[mt], (uint32_t)__cvta_generic_to_shared(&sAl[st][row * AS + col]));
        }
        uint32_t bh[NT][2], bl[NT][2];
#pragma unroll
        for (int nt = 0; nt < NT; ++nt) {
            int col = wn * (BN / 2) + nt * 8;
            int row = lane & 15;
            ldsm_x2t(bh[nt], (uint32_t)__cvta_generic_to_shared(&sBh[st][row * BS + col]));
            ldsm_x2t(bl[nt], (uint32_t)__cvta_generic_to_shared(&sBl[st][row * BS + col]));
        }
#pragma unroll
        for (int mt = 0; mt < 2; ++mt)
#pragma unroll
            for (int nt = 0; nt < NT; ++nt) {
                mma16816(acc[mt][nt], ah[mt], bh[nt]);   // hi*hi
                mma16816(acc[mt][nt], al[mt], bh[nt]);   // lo*hi
                mma16816(acc[mt][nt], ah[mt], bl[nt]);   // hi*lo
            }
        __syncthreads();   // protect stage st before it is re-filled at tt+1
    }

    // ---- epilogue (rs_out row-scale folded in)
#pragma unroll
    for (int mt = 0; mt < 2; ++mt) {
        int gr0 = rowBase + wm * 32 + mt * 16 + (lane >> 2);
        int gc0 = wn * (BN / 2) + (lane & 3) * 2;
        float s0 = (gr0 < M)     ? __ldg(&rsR[gr0])     : 0.f;
        float s1 = (gr0 + 8 < M) ? __ldg(&rsR[gr0 + 8]) : 0.f;
#pragma unroll
        for (int nt = 0; nt < NT; ++nt) {
            int c = gc0 + nt * 8;
            if (gr0 < M)
                *reinterpret_cast<float2*>(YR + (size_t)gr0 * BN + c) =
                    make_float2(s0 * acc[mt][nt][0], s0 * acc[mt][nt][1]);
            if (gr0 + 8 < M)
                *reinterpret_cast<float2*>(YR + (size_t)(gr0 + 8) * BN + c) =
                    make_float2(s1 * acc[mt][nt][2], s1 * acc[mt][nt][3]);
        }
    }
}

// ---------------------------------------------------------------------------
// Edge scatter, all relations in one launch, vector REDs (RED/LTS-bound):
//   acc[d] += rs_in_r[d] * Y[r][s, :]      (rs_out folded into Y)
// ---------------------------------------------------------------------------
__global__ __launch_bounds__(256)
void scatter_f128_kernel(const float* __restrict__ Y,
                         const int* __restrict__ esrc,
                         const int* __restrict__ edst,
                         const float* __restrict__ rs_in,
                         float* __restrict__ acc) {
    int gw = (blockIdx.x * blockDim.x + threadIdx.x) >> 5;
    int lane = threadIdx.x & 31;
    if (gw >= RR * EE) return;
    int r = gw / EE;
    int s = esrc[gw];
    int d = edst[gw];
    float c = __ldg(&rs_in[r * NN + d]);
    float4 v = *reinterpret_cast<const float4*>(Y + ((size_t)r * NN + s) * HIDF + lane * 4);
    float* p = acc + (size_t)d * HIDF + lane * 4;
    asm volatile("red.global.add.v4.f32 [%0], {%1,%2,%3,%4};"
                 :: "l"(p), "f"(c * v.x), "f"(c * v.y), "f"(c * v.z), "f"(c * v.w)
                 : "memory");
}

__global__ __launch_bounds__(256)
void scatter_f64_kernel(const float* __restrict__ Y,
                        const int* __restrict__ esrc,
                        const int* __restrict__ edst,
                        const float* __restrict__ rs_in,
                        float* __restrict__ acc) {
    int gw = (blockIdx.x * blockDim.x + threadIdx.x) >> 5;
    int lane = threadIdx.x & 31;
    if (gw >= RR * EE) return;
    int r = gw / EE;
    int s = esrc[gw];
    int d = edst[gw];
    float c = __ldg(&rs_in[r * NN + d]);
    float2 v = *reinterpret_cast<const float2*>(Y + ((size_t)r * NN + s) * OUTF + lane * 2);
    float* p = acc + (size_t)d * OUTF + lane * 2;
    asm volatile("red.global.add.v2.f32 [%0], {%1,%2};"
                 :: "l"(p), "f"(c * v.x), "f"(c * v.y)
                 : "memory");
}

// ---------------------------------------------------------------------------
// Launch
// ---------------------------------------------------------------------------
extern "C" void kernel_launch(void* const* d_in, const int* in_sizes, int n_in,
                              void* d_out, int out_size) {
    const float* x    = (const float*)d_in[0];
    const int*   esrc = (const int*)  d_in[1];
    const int*   edst = (const int*)  d_in[2];
    const float* W1   = (const float*)d_in[3];
    const float* b1   = (const float*)d_in[4];
    const float* W2   = (const float*)d_in[5];
    const float* b2   = (const float*)d_in[6];
    float* out = (float*)d_out;

    __nv_bfloat16 *xhi, *xlo, *w1hi, *w1lo, *w2hi, *w2lo, *a2hi, *a2lo;
    float *Y1, *Y2, *acc1, *rs_out, *rs_in;
    int *cnt_out, *cnt_in;
    cudaGetSymbolAddress((void**)&xhi,     g_xhi);
    cudaGetSymbolAddress((void**)&xlo,     g_xlo);
    cudaGetSymbolAddress((void**)&w1hi,    g_w1hi);
    cudaGetSymbolAddress((void**)&w1lo,    g_w1lo);
    cudaGetSymbolAddress((void**)&w2hi,    g_w2hi);
    cudaGetSymbolAddress((void**)&w2lo,    g_w2lo);
    cudaGetSymbolAddress((void**)&a2hi,    g_a2hi);
    cudaGetSymbolAddress((void**)&a2lo,    g_a2lo);
    cudaGetSymbolAddress((void**)&Y1,      g_Y1);
    cudaGetSymbolAddress((void**)&Y2,      g_Y2);
    cudaGetSymbolAddress((void**)&acc1,    g_acc1);
    cudaGetSymbolAddress((void**)&cnt_out, g_cnt_out);
    cudaGetSymbolAddress((void**)&cnt_in,  g_cnt_in);
    cudaGetSymbolAddress((void**)&rs_out,  g_rs_out);
    cudaGetSymbolAddress((void**)&rs_in,   g_rs_in);

    const int TPB = 256;

    // ---- degrees ----
    cudaMemsetAsync(cnt_out, 0, RR * NN * sizeof(int));
    cudaMemsetAsync(cnt_in,  0, RR * NN * sizeof(int));
    degree_count_kernel<<<(RR * EE + TPB - 1) / TPB, TPB>>>(esrc, edst, cnt_out, cnt_in);
    rs_kernel<<<(RR * NN + TPB - 1) / TPB, TPB>>>(cnt_out, cnt_in, rs_out, rs_in);

    // ---- bf16 splits of inputs/weights ----
    {
        int nx = NN * INF;
        split_kernel<false><<<(nx / 4 + TPB - 1) / TPB, TPB>>>(x, xhi, xlo, nx);
        int nw1 = RR * INF * HIDF;
        split_kernel<false><<<(nw1 / 4 + TPB - 1) / TPB, TPB>>>(W1, w1hi, w1lo, nw1);
        int nw2 = RR * HIDF * OUTF;
        split_kernel<false><<<(nw2 / 4 + TPB - 1) / TPB, TPB>>>(W2, w2hi, w2lo, nw2);
    }

    const dim3 gemmGrid((NN + 127) / 128, RR);
    const int scatterGrid = (RR * EE * 32 + TPB - 1) / TPB;

    // ---- Layer 1 ----
    init_bias_kernel<HIDF><<<(NN * HIDF / 4 + TPB - 1) / TPB, TPB>>>(acc1, b1);
    gemm_bf16_pipe_kernel<HIDF><<<gemmGrid, TPB>>>(xhi, xlo, w1hi, w1lo, rs_out, Y1, NN, INF);
    scatter_f128_kernel<<<scatterGrid, TPB>>>(Y1, esrc, edst, rs_in, acc1);

    // ---- ReLU + split for layer 2 ----
    {
        int n = NN * HIDF;
        split_kernel<true><<<(n / 4 + TPB - 1) / TPB, TPB>>>(acc1, a2hi, a2lo, n);
    }

    // ---- Layer 2 ----
    init_bias_kernel<OUTF><<<(NN * OUTF / 4 + TPB - 1) / TPB, TPB>>>(out, b2);
    gemm_bf16_pipe_kernel<OUTF><<<gemmGrid, TPB>>>(a2hi, a2lo, w2hi, w2lo, rs_out, Y2, NN, HIDF);
    scatter_f64_kernel<<<scatterGrid, TPB>>>(Y2, esrc, edst, rs_in, out);
}

// round 11
// speedup vs baseline: 1.5785x; 1.4478x over previous
#include <cuda_runtime.h>
#include <cuda_bf16.h>
#include <cstdint>

// Problem constants
#define NN   100000   // nodes
#define RR   4        // relations
#define EE   500000   // edges per relation
#define INF  256
#define HIDF 128
#define OUTF 64

// ---------------------------------------------------------------------------
// Static device scratch (allocation-free per harness rules)
// ---------------------------------------------------------------------------
static __device__ __nv_bfloat16 g_xhi[(size_t)NN * INF];     // 51.2 MB
static __device__ __nv_bfloat16 g_xlo[(size_t)NN * INF];     // 51.2 MB
static __device__ __nv_bfloat16 g_w1hi[RR * INF * HIDF];
static __device__ __nv_bfloat16 g_w1lo[RR * INF * HIDF];
static __device__ __nv_bfloat16 g_w2hi[RR * HIDF * OUTF];
static __device__ __nv_bfloat16 g_w2lo[RR * HIDF * OUTF];
static __device__ __nv_bfloat16 g_a2hi[(size_t)NN * HIDF];   // 25.6 MB
static __device__ __nv_bfloat16 g_a2lo[(size_t)NN * HIDF];   // 25.6 MB
static __device__ float g_Y1[(size_t)RR * NN * HIDF];        // 204.8 MB  [r*NN+n][128]
static __device__ float g_Y2[(size_t)RR * NN * OUTF];        // 102.4 MB  [r*NN+n][64]
static __device__ int   g_cnt_out[RR * NN];
static __device__ int   g_cnt_in[RR * NN];
static __device__ float g_rs_out[RR * NN];
static __device__ float g_rs_in[RR * NN];
static __device__ int   g_offs[NN];                          // dst-CSR segment starts (all rel)
static __device__ int   g_dcnt[NN];                          // total in-degree per dst
static __device__ int   g_cur[NN];                           // fill cursors
static __device__ int   g_ctr[1];                            // bump allocator
static __device__ int2  g_csr[(size_t)RR * EE];              // (r*NN+src, bits(rs_in_r[dst])) 16 MB

// ---------------------------------------------------------------------------
// Tensor-core / async-copy primitives
// ---------------------------------------------------------------------------
__device__ __forceinline__ void ldsm_x4(uint32_t* r, uint32_t a) {
    asm volatile("ldmatrix.sync.aligned.m8n8.x4.shared.b16 {%0,%1,%2,%3}, [%4];"
                 : "=r"(r[0]), "=r"(r[1]), "=r"(r[2]), "=r"(r[3]) : "r"(a));
}
__device__ __forceinline__ void ldsm_x2t(uint32_t* r, uint32_t a) {
    asm volatile("ldmatrix.sync.aligned.m8n8.x2.trans.shared.b16 {%0,%1}, [%2];"
                 : "=r"(r[0]), "=r"(r[1]) : "r"(a));
}
__device__ __forceinline__ void mma16816(float* c, const uint32_t* a, const uint32_t* b) {
    asm volatile(
        "mma.sync.aligned.m16n8k16.row.col.f32.bf16.bf16.f32 "
        "{%0,%1,%2,%3}, {%4,%5,%6,%7}, {%8,%9}, {%0,%1,%2,%3};"
        : "+f"(c[0]), "+f"(c[1]), "+f"(c[2]), "+f"(c[3])
        : "r"(a[0]), "r"(a[1]), "r"(a[2]), "r"(a[3]), "r"(b[0]), "r"(b[1]));
}
__device__ __forceinline__ void cp_async16(void* smem, const void* gmem, bool pred) {
    uint32_t s = (uint32_t)__cvta_generic_to_shared(smem);
    int sz = pred ? 16 : 0;
    asm volatile("cp.async.cg.shared.global [%0], [%1], 16, %2;"
                 :: "r"(s), "l"(gmem), "r"(sz));
}
__device__ __forceinline__ void cp_commit() {
    asm volatile("cp.async.commit_group;");
}
template <int N>
__device__ __forceinline__ void cp_wait() {
    asm volatile("cp.async.wait_group %0;" :: "n"(N));
}

// ---------------------------------------------------------------------------
// Preprocessing kernels
// ---------------------------------------------------------------------------
__global__ void degree_count_kernel(const int* __restrict__ src,
                                    const int* __restrict__ dst,
                                    int* __restrict__ cnt_out,
                                    int* __restrict__ cnt_in) {
    int i = blockIdx.x * blockDim.x + threadIdx.x;
    if (i >= RR * EE) return;
    int r = i / EE;
    atomicAdd(&cnt_out[r * NN + src[i]], 1);
    atomicAdd(&cnt_in [r * NN + dst[i]], 1);
}

__global__ void rs_kernel(const int* __restrict__ cnt_out,
                          const int* __restrict__ cnt_in,
                          float* __restrict__ rs_out,
                          float* __restrict__ rs_in) {
    int i = blockIdx.x * blockDim.x + threadIdx.x;
    if (i >= RR * NN) return;
    rs_out[i] = rsqrtf((float)max(cnt_out[i], 1));
    rs_in [i] = rsqrtf((float)max(cnt_in [i], 1));
}

// One segment per dst covering ALL relations (order irrelevant; sums commute).
__global__ void alloc_offsets_kernel(const int* __restrict__ cnt_in,
                                     int* __restrict__ offs,
                                     int* __restrict__ dcnt,
                                     int* __restrict__ cur,
                                     int* __restrict__ ctr) {
    int d = blockIdx.x * blockDim.x + threadIdx.x;
    if (d >= NN) return;
    int c = cnt_in[0 * NN + d] + cnt_in[1 * NN + d] + cnt_in[2 * NN + d] + cnt_in[3 * NN + d];
    int off = atomicAdd(ctr, c);
    offs[d] = off;
    dcnt[d] = c;
    cur[d]  = off;
}

__global__ void csr_fill_kernel(const int* __restrict__ src,
                                const int* __restrict__ dst,
                                const float* __restrict__ rs_in,
                                int* __restrict__ cur,
                                int2* __restrict__ csr) {
    int i = blockIdx.x * blockDim.x + threadIdx.x;
    if (i >= RR * EE) return;
    int r = i / EE;
    int s = src[i];
    int d = dst[i];
    int pos = atomicAdd(&cur[d], 1);
    csr[pos] = make_int2(r * NN + s, __float_as_int(__ldg(&rs_in[r * NN + d])));
}

// Split fp32 -> (hi, lo) bf16 pair. n % 4 == 0.
__global__ void split_kernel(const float* __restrict__ in,
                             __nv_bfloat16* __restrict__ hi,
                             __nv_bfloat16* __restrict__ lo, int n) {
    int i4 = (blockIdx.x * blockDim.x + threadIdx.x) * 4;
    if (i4 >= n) return;
    float4 v = *reinterpret_cast<const float4*>(in + i4);
    __nv_bfloat16 hx = __float2bfloat16(v.x), hy = __float2bfloat16(v.y);
    __nv_bfloat16 hz = __float2bfloat16(v.z), hw = __float2bfloat16(v.w);
    float lx = v.x - __bfloat162float(hx), ly = v.y - __bfloat162float(hy);
    float lz = v.z - __bfloat162float(hz), lw = v.w - __bfloat162float(hw);
    __nv_bfloat162* H = reinterpret_cast<__nv_bfloat162*>(hi + i4);
    __nv_bfloat162* L = reinterpret_cast<__nv_bfloat162*>(lo + i4);
    H[0] = __halves2bfloat162(hx, hy);
    H[1] = __halves2bfloat162(hz, hw);
    L[0] = __halves2bfloat162(__float2bfloat16(lx), __float2bfloat16(ly));
    L[1] = __halves2bfloat162(__float2bfloat16(lz), __float2bfloat16(lw));
}

// ---------------------------------------------------------------------------
// Pipelined tensor-core GEMM (3-term bf16 split), batched over relations:
//   Y[(rel*NN + m), 0:BN] = rs_out_rel[m] * (A[m, :] @ W_rel[:, 0:BN])
// BM=128, BK=16, 2-stage cp.async double buffer, 256 threads (8 warps).
// ---------------------------------------------------------------------------
template <int BN>
__global__ __launch_bounds__(256)
void gemm_bf16_pipe_kernel(const __nv_bfloat16* __restrict__ Ahi,
                           const __nv_bfloat16* __restrict__ Alo,
                           const __nv_bfloat16* __restrict__ Whi,
                           const __nv_bfloat16* __restrict__ Wlo,
                           const float* __restrict__ rs_out,
                           float* __restrict__ Y,
                           int M, int K) {
    constexpr int BM = 128;
    constexpr int BK = 16;
    constexpr int NT = BN / 16;
    constexpr int AS = BK + 8;
    constexpr int BS = BN + 8;
    constexpr int BCH = 2 * BN;       // 16-byte chunks per B tile

    __shared__ __align__(16) __nv_bfloat16 sAh[2][BM * AS], sAl[2][BM * AS];
    __shared__ __align__(16) __nv_bfloat16 sBh[2][BK * BS], sBl[2][BK * BS];

    const int t = threadIdx.x;
    const int lane = t & 31;
    const int wid = t >> 5;
    const int wm = wid & 3;
    const int wn = wid >> 2;
    const int rowBase = blockIdx.x * BM;
    const int rel = blockIdx.y;

    const __nv_bfloat16* WhiR = Whi + (size_t)rel * K * BN;
    const __nv_bfloat16* WloR = Wlo + (size_t)rel * K * BN;
    const float* rsR = rs_out + rel * NN;
    float* YR = Y + (size_t)rel * NN * BN;

    const int arow = t >> 1;
    const int acol = (t & 1) * 8;
    const int agr  = rowBase + arow;
    const bool apred = agr < M;
    const int brow = t / (BN / 8);
    const int bc8  = (t % (BN / 8)) * 8;

    float acc[2][NT][4];
#pragma unroll
    for (int mt = 0; mt < 2; ++mt)
#pragma unroll
        for (int nt = 0; nt < NT; ++nt)
#pragma unroll
            for (int j = 0; j < 4; ++j) acc[mt][nt][j] = 0.f;

    const int ntiles = K / BK;

    {
        cp_async16(&sAh[0][arow * AS + acol], Ahi + (size_t)agr * K + acol, apred);
        cp_async16(&sAl[0][arow * AS + acol], Alo + (size_t)agr * K + acol, apred);
        if (t < BCH) {
            cp_async16(&sBh[0][brow * BS + bc8], WhiR + (size_t)brow * BN + bc8, true);
            cp_async16(&sBl[0][brow * BS + bc8], WloR + (size_t)brow * BN + bc8, true);
        }
        cp_commit();
    }

    for (int tt = 0; tt < ntiles; ++tt) {
        int st = tt & 1;
        if (tt + 1 < ntiles) {
            int ns = st ^ 1;
            int k0 = (tt + 1) * BK;
            cp_async16(&sAh[ns][arow * AS + acol], Ahi + (size_t)agr * K + k0 + acol, apred);
            cp_async16(&sAl[ns][arow * AS + acol], Alo + (size_t)agr * K + k0 + acol, apred);
            if (t < BCH) {
                cp_async16(&sBh[ns][brow * BS + bc8], WhiR + (size_t)(k0 + brow) * BN + bc8, true);
                cp_async16(&sBl[ns][brow * BS + bc8], WloR + (size_t)(k0 + brow) * BN + bc8, true);
            }
            cp_commit();
            cp_wait<1>();
        } else {
            cp_wait<0>();
        }
        __syncthreads();

        uint32_t ah[2][4], al[2][4];
#pragma unroll
        for (int mt = 0; mt < 2; ++mt) {
            int row = wm * 32 + mt * 16 + (lane & 15);
            int col = (lane >> 4) * 8;
            ldsm_x4(ah[mt], (uint32_t)__cvta_generic_to_shared(&sAh[st][row * AS + col]));
            ldsm_x4(al[mt], (uint32_t)__cvta_generic_to_shared(&sAl[st][row * AS + col]));
        }
        uint32_t bh[NT][2], bl[NT][2];
#pragma unroll
        for (int nt = 0; nt < NT; ++nt) {
            int col = wn * (BN / 2) + nt * 8;
            int row = lane & 15;
            ldsm_x2t(bh[nt], (uint32_t)__cvta_generic_to_shared(&sBh[st][row * BS + col]));
            ldsm_x2t(bl[nt], (uint32_t)__cvta_generic_to_shared(&sBl[st][row * BS + col]));
        }
#pragma unroll
        for (int mt = 0; mt < 2; ++mt)
#pragma unroll
            for (int nt = 0; nt < NT; ++nt) {
                mma16816(acc[mt][nt], ah[mt], bh[nt]);
                mma16816(acc[mt][nt], al[mt], bh[nt]);
                mma16816(acc[mt][nt], ah[mt], bl[nt]);
            }
        __syncthreads();
    }

#pragma unroll
    for (int mt = 0; mt < 2; ++mt) {
        int gr0 = rowBase + wm * 32 + mt * 16 + (lane >> 2);
        int gc0 = wn * (BN / 2) + (lane & 3) * 2;
        float s0 = (gr0 < M)     ? __ldg(&rsR[gr0])     : 0.f;
        float s1 = (gr0 + 8 < M) ? __ldg(&rsR[gr0 + 8]) : 0.f;
#pragma unroll
        for (int nt = 0; nt < NT; ++nt) {
            int c = gc0 + nt * 8;
            if (gr0 < M)
                *reinterpret_cast<float2*>(YR + (size_t)gr0 * BN + c) =
                    make_float2(s0 * acc[mt][nt][0], s0 * acc[mt][nt][1]);
            if (gr0 + 8 < M)
                *reinterpret_cast<float2*>(YR + (size_t)(gr0 + 8) * BN + c) =
                    make_float2(s1 * acc[mt][nt][2], s1 * acc[mt][nt][3]);
        }
    }
}

// ---------------------------------------------------------------------------
// Layer-1 gather: warp per dst. shfl-batched edge records -> independent
// 512-B row gathers (MLP ~ degree). Fused bias + ReLU + bf16 split epilogue.
//   h[d] = relu( sum_e coeff_e * Y1[yidx_e, :] + sum_r b1[r] ) -> (a2hi, a2lo)
// ---------------------------------------------------------------------------
__global__ __launch_bounds__(256)
void gather_l1_kernel(const float* __restrict__ Y,
                      const int2* __restrict__ csr,
                      const int* __restrict__ offs,
                      const int* __restrict__ dcnt,
                      const float* __restrict__ b1,
                      __nv_bfloat16* __restrict__ a2hi,
                      __nv_bfloat16* __restrict__ a2lo) {
    int d = (blockIdx.x * blockDim.x + threadIdx.x) >> 5;
    if (d >= NN) return;
    int lane = threadIdx.x & 31;
    int n = dcnt[d];
    const int2* ep = csr + offs[d];

    float4 tot = make_float4(0.f, 0.f, 0.f, 0.f);
    for (int base = 0; base < n; base += 32) {
        int m = min(32, n - base);
        int2 rec = make_int2(0, 0);
        if (lane < m) rec = __ldg(ep + base + lane);
#pragma unroll 4
        for (int j = 0; j < m; ++j) {
            int yi  = __shfl_sync(0xffffffffu, rec.x, j);
            float c = __int_as_float(__shfl_sync(0xffffffffu, rec.y, j));
            float4 v = *reinterpret_cast<const float4*>(Y + (size_t)yi * HIDF + lane * 4);
            tot.x += c * v.x; tot.y += c * v.y;
            tot.z += c * v.z; tot.w += c * v.w;
        }
    }
#pragma unroll
    for (int r = 0; r < RR; ++r) {
        float4 bv = *reinterpret_cast<const float4*>(b1 + r * HIDF + lane * 4);
        tot.x += bv.x; tot.y += bv.y; tot.z += bv.z; tot.w += bv.w;
    }
    tot.x = fmaxf(tot.x, 0.f); tot.y = fmaxf(tot.y, 0.f);
    tot.z = fmaxf(tot.z, 0.f); tot.w = fmaxf(tot.w, 0.f);

    __nv_bfloat16 h0 = __float2bfloat16(tot.x), h1 = __float2bfloat16(tot.y);
    __nv_bfloat16 h2 = __float2bfloat16(tot.z), h3 = __float2bfloat16(tot.w);
    __nv_bfloat162 hA = __halves2bfloat162(h0, h1), hB = __halves2bfloat162(h2, h3);
    __nv_bfloat162 lA = __halves2bfloat162(__float2bfloat16(tot.x - __bfloat162float(h0)),
                                           __float2bfloat16(tot.y - __bfloat162float(h1)));
    __nv_bfloat162 lB = __halves2bfloat162(__float2bfloat16(tot.z - __bfloat162float(h2)),
                                           __float2bfloat16(tot.w - __bfloat162float(h3)));
    uint2 hv = make_uint2(*reinterpret_cast<uint32_t*>(&hA), *reinterpret_cast<uint32_t*>(&hB));
    uint2 lv = make_uint2(*reinterpret_cast<uint32_t*>(&lA), *reinterpret_cast<uint32_t*>(&lB));
    *reinterpret_cast<uint2*>(a2hi + (size_t)d * HIDF + lane * 4) = hv;
    *reinterpret_cast<uint2*>(a2lo + (size_t)d * HIDF + lane * 4) = lv;
}

// ---------------------------------------------------------------------------
// Layer-2 gather: warp per dst, 2 floats/lane. Fused bias; writes output.
// ---------------------------------------------------------------------------
__global__ __launch_bounds__(256)
void gather_l2_kernel(const float* __restrict__ Y,
                      const int2* __restrict__ csr,
                      const int* __restrict__ offs,
                      const int* __restrict__ dcnt,
                      const float* __restrict__ b2,
                      float* __restrict__ out) {
    int d = (blockIdx.x * blockDim.x + threadIdx.x) >> 5;
    if (d >= NN) return;
    int lane = threadIdx.x & 31;
    int n = dcnt[d];
    const int2* ep = csr + offs[d];

    float2 tot = make_float2(0.f, 0.f);
    for (int base = 0; base < n; base += 32) {
        int m = min(32, n - base);
        int2 rec = make_int2(0, 0);
        if (lane < m) rec = __ldg(ep + base + lane);
#pragma unroll 4
        for (int j = 0; j < m; ++j) {
            int yi  = __shfl_sync(0xffffffffu, rec.x, j);
            float c = __int_as_float(__shfl_sync(0xffffffffu, rec.y, j));
            float2 v = *reinterpret_cast<const float2*>(Y + (size_t)yi * OUTF + lane * 2);
            tot.x += c * v.x; tot.y += c * v.y;
        }
    }
#pragma unroll
    for (int r = 0; r < RR; ++r) {
        float2 bv = *reinterpret_cast<const float2*>(b2 + r * OUTF + lane * 2);
        tot.x += bv.x; tot.y += bv.y;
    }
    *reinterpret_cast<float2*>(out + (size_t)d * OUTF + lane * 2) = tot;
}

// ---------------------------------------------------------------------------
// Launch
// ---------------------------------------------------------------------------
extern "C" void kernel_launch(void* const* d_in, const int* in_sizes, int n_in,
                              void* d_out, int out_size) {
    const float* x    = (const float*)d_in[0];
    const int*   esrc = (const int*)  d_in[1];
    const int*   edst = (const int*)  d_in[2];
    const float* W1   = (const float*)d_in[3];
    const float* b1   = (const float*)d_in[4];
    const float* W2   = (const float*)d_in[5];
    const float* b2   = (const float*)d_in[6];
    float* out = (float*)d_out;

    __nv_bfloat16 *xhi, *xlo, *w1hi, *w1lo, *w2hi, *w2lo, *a2hi, *a2lo;
    float *Y1, *Y2, *rs_out, *rs_in;
    int *cnt_out, *cnt_in, *offs, *dcnt, *cur, *ctr;
    int2* csr;
    cudaGetSymbolAddress((void**)&xhi,     g_xhi);
    cudaGetSymbolAddress((void**)&xlo,     g_xlo);
    cudaGetSymbolAddress((void**)&w1hi,    g_w1hi);
    cudaGetSymbolAddress((void**)&w1lo,    g_w1lo);
    cudaGetSymbolAddress((void**)&w2hi,    g_w2hi);
    cudaGetSymbolAddress((void**)&w2lo,    g_w2lo);
    cudaGetSymbolAddress((void**)&a2hi,    g_a2hi);
    cudaGetSymbolAddress((void**)&a2lo,    g_a2lo);
    cudaGetSymbolAddress((void**)&Y1,      g_Y1);
    cudaGetSymbolAddress((void**)&Y2,      g_Y2);
    cudaGetSymbolAddress((void**)&cnt_out, g_cnt_out);
    cudaGetSymbolAddress((void**)&cnt_in,  g_cnt_in);
    cudaGetSymbolAddress((void**)&rs_out,  g_rs_out);
    cudaGetSymbolAddress((void**)&rs_in,   g_rs_in);
    cudaGetSymbolAddress((void**)&offs,    g_offs);
    cudaGetSymbolAddress((void**)&dcnt,    g_dcnt);
    cudaGetSymbolAddress((void**)&cur,     g_cur);
    cudaGetSymbolAddress((void**)&ctr,     g_ctr);
    cudaGetSymbolAddress((void**)&csr,     g_csr);

    const int TPB = 256;

    // ---- degrees + all-relation dst-CSR ----
    cudaMemsetAsync(cnt_out, 0, RR * NN * sizeof(int));
    cudaMemsetAsync(cnt_in,  0, RR * NN * sizeof(int));
    cudaMemsetAsync(ctr,     0, sizeof(int));
    degree_count_kernel<<<(RR * EE + TPB - 1) / TPB, TPB>>>(esrc, edst, cnt_out, cnt_in);
    rs_kernel<<<(RR * NN + TPB - 1) / TPB, TPB>>>(cnt_out, cnt_in, rs_out, rs_in);
    alloc_offsets_kernel<<<(NN + TPB - 1) / TPB, TPB>>>(cnt_in, offs, dcnt, cur, ctr);
    csr_fill_kernel<<<(RR * EE + TPB - 1) / TPB, TPB>>>(esrc, edst, rs_in, cur, csr);

    // ---- bf16 splits of inputs/weights ----
    {
        int nx = NN * INF;
        split_kernel<<<(nx / 4 + TPB - 1) / TPB, TPB>>>(x, xhi, xlo, nx);
        int nw1 = RR * INF * HIDF;
        split_kernel<<<(nw1 / 4 + TPB - 1) / TPB, TPB>>>(W1, w1hi, w1lo, nw1);
        int nw2 = RR * HIDF * OUTF;
        split_kernel<<<(nw2 / 4 + TPB - 1) / TPB, TPB>>>(W2, w2hi, w2lo, nw2);
    }

    const dim3 gemmGrid((NN + 127) / 128, RR);
    const int gatherGrid = (NN * 32 + TPB - 1) / TPB;   // warp per dst

    // ---- Layer 1: GEMM -> gather (bias+ReLU+split fused) ----
    gemm_bf16_pipe_kernel<HIDF><<<gemmGrid, TPB>>>(xhi, xlo, w1hi, w1lo, rs_out, Y1, NN, INF);
    gather_l1_kernel<<<gatherGrid, TPB>>>(Y1, csr, offs, dcnt, b1, a2hi, a2lo);

    // ---- Layer 2: GEMM -> gather (bias fused, writes out) ----
    gemm_bf16_pipe_kernel<OUTF><<<gemmGrid, TPB>>>(a2hi, a2lo, w2hi, w2lo, rs_out, Y2, NN, HIDF);
    gather_l2_kernel<<<gatherGrid, TPB>>>(Y2, csr, offs, dcnt, b2, out);
}

// round 12
// speedup vs baseline: 1.6203x; 1.0265x over previous
#include <cuda_runtime.h>
#include <cuda_bf16.h>
#include <cstdint>

// Problem constants
#define NN   100000   // nodes
#define RR   4        // relations
#define EE   500000   // edges per relation
#define INF  256
#define HIDF 128
#define OUTF 64

// ---------------------------------------------------------------------------
// Static device scratch (allocation-free per harness rules)
// ---------------------------------------------------------------------------
static __device__ __nv_bfloat16 g_xhi[(size_t)NN * INF];     // 51.2 MB
static __device__ __nv_bfloat16 g_xlo[(size_t)NN * INF];     // 51.2 MB
static __device__ __nv_bfloat16 g_w1hi[RR * INF * HIDF];
static __device__ __nv_bfloat16 g_w1lo[RR * INF * HIDF];
static __device__ __nv_bfloat16 g_w2hi[RR * HIDF * OUTF];
static __device__ __nv_bfloat16 g_w2lo[RR * HIDF * OUTF];
static __device__ __nv_bfloat16 g_a2hi[(size_t)NN * HIDF];   // 25.6 MB
static __device__ __nv_bfloat16 g_a2lo[(size_t)NN * HIDF];   // 25.6 MB
static __device__ float g_Y1[(size_t)RR * NN * HIDF];        // 204.8 MB  [r*NN+n][128]
static __device__ float g_Y2[(size_t)RR * NN * OUTF];        // 102.4 MB  [r*NN+n][64]
// counters block: [cnt_out RR*NN | cnt_in RR*NN | ctr 1] -> single memset
static __device__ int   g_cnt[2 * RR * NN + 1];
static __device__ float g_rs_out[RR * NN];
static __device__ float g_rs_in[RR * NN];
static __device__ int   g_offs[NN];                          // dst-CSR segment starts (all rel)
static __device__ int   g_dcnt[NN];                          // total in-degree per dst
static __device__ int   g_cur[NN];                           // fill cursors
static __device__ int2  g_csr[(size_t)RR * EE];              // (r*NN+src, bits(rs_in_r[dst])) 16 MB

// ---------------------------------------------------------------------------
// Tensor-core / async-copy primitives
// ---------------------------------------------------------------------------
__device__ __forceinline__ void ldsm_x4(uint32_t* r, uint32_t a) {
    asm volatile("ldmatrix.sync.aligned.m8n8.x4.shared.b16 {%0,%1,%2,%3}, [%4];"
                 : "=r"(r[0]), "=r"(r[1]), "=r"(r[2]), "=r"(r[3]) : "r"(a));
}
__device__ __forceinline__ void ldsm_x2t(uint32_t* r, uint32_t a) {
    asm volatile("ldmatrix.sync.aligned.m8n8.x2.trans.shared.b16 {%0,%1}, [%2];"
                 : "=r"(r[0]), "=r"(r[1]) : "r"(a));
}
__device__ __forceinline__ void mma16816(float* c, const uint32_t* a, const uint32_t* b) {
    asm volatile(
        "mma.sync.aligned.m16n8k16.row.col.f32.bf16.bf16.f32 "
        "{%0,%1,%2,%3}, {%4,%5,%6,%7}, {%8,%9}, {%0,%1,%2,%3};"
        : "+f"(c[0]), "+f"(c[1]), "+f"(c[2]), "+f"(c[3])
        : "r"(a[0]), "r"(a[1]), "r"(a[2]), "r"(a[3]), "r"(b[0]), "r"(b[1]));
}
__device__ __forceinline__ void cp_async16(void* smem, const void* gmem, bool pred) {
    uint32_t s = (uint32_t)__cvta_generic_to_shared(smem);
    int sz = pred ? 16 : 0;
    asm volatile("cp.async.cg.shared.global [%0], [%1], 16, %2;"
                 :: "r"(s), "l"(gmem), "r"(sz));
}
__device__ __forceinline__ void cp_commit() {
    asm volatile("cp.async.commit_group;");
}
template <int N>
__device__ __forceinline__ void cp_wait() {
    asm volatile("cp.async.wait_group %0;" :: "n"(N));
}

// ---------------------------------------------------------------------------
// Preprocessing kernels
// ---------------------------------------------------------------------------
__global__ void degree_count_kernel(const int* __restrict__ src,
                                    const int* __restrict__ dst,
                                    int* __restrict__ cnt_out,
                                    int* __restrict__ cnt_in) {
    int i = blockIdx.x * blockDim.x + threadIdx.x;
    if (i >= RR * EE) return;
    int r = i / EE;
    atomicAdd(&cnt_out[r * NN + src[i]], 1);
    atomicAdd(&cnt_in [r * NN + dst[i]], 1);
}

__global__ void rs_kernel(const int* __restrict__ cnt_out,
                          const int* __restrict__ cnt_in,
                          float* __restrict__ rs_out,
                          float* __restrict__ rs_in) {
    int i = blockIdx.x * blockDim.x + threadIdx.x;
    if (i >= RR * NN) return;
    rs_out[i] = rsqrtf((float)max(cnt_out[i], 1));
    rs_in [i] = rsqrtf((float)max(cnt_in [i], 1));
}

// Segment per dst covering ALL relations; two-level bump allocation
// (shared-counter per block + one global atomic per block) to avoid
// serializing 100k atomics on one L2 address.
__global__ void alloc_offsets_kernel(const int* __restrict__ cnt_in,
                                     int* __restrict__ offs,
                                     int* __restrict__ dcnt,
                                     int* __restrict__ cur,
                                     int* __restrict__ ctr) {
    __shared__ int sctr, sbase;
    if (threadIdx.x == 0) sctr = 0;
    __syncthreads();
    int d = blockIdx.x * blockDim.x + threadIdx.x;
    int c = 0, local = 0;
    if (d < NN) {
        c = cnt_in[0 * NN + d] + cnt_in[1 * NN + d] +
            cnt_in[2 * NN + d] + cnt_in[3 * NN + d];
        local = atomicAdd(&sctr, c);
    }
    __syncthreads();
    if (threadIdx.x == 0) sbase = atomicAdd(ctr, sctr);
    __syncthreads();
    if (d < NN) {
        int off = sbase + local;
        offs[d] = off;
        dcnt[d] = c;
        cur[d]  = off;
    }
}

__global__ void csr_fill_kernel(const int* __restrict__ src,
                                const int* __restrict__ dst,
                                const float* __restrict__ rs_in,
                                int* __restrict__ cur,
                                int2* __restrict__ csr) {
    int i = blockIdx.x * blockDim.x + threadIdx.x;
    if (i >= RR * EE) return;
    int r = i / EE;
    int s = src[i];
    int d = dst[i];
    int pos = atomicAdd(&cur[d], 1);
    csr[pos] = make_int2(r * NN + s, __float_as_int(__ldg(&rs_in[r * NN + d])));
}

// Split fp32 -> (hi, lo) bf16 pair. n % 4 == 0.
__global__ void split_kernel(const float* __restrict__ in,
                             __nv_bfloat16* __restrict__ hi,
                             __nv_bfloat16* __restrict__ lo, int n) {
    int i4 = (blockIdx.x * blockDim.x + threadIdx.x) * 4;
    if (i4 >= n) return;
    float4 v = *reinterpret_cast<const float4*>(in + i4);
    __nv_bfloat16 hx = __float2bfloat16(v.x), hy = __float2bfloat16(v.y);
    __nv_bfloat16 hz = __float2bfloat16(v.z), hw = __float2bfloat16(v.w);
    float lx = v.x - __bfloat162float(hx), ly = v.y - __bfloat162float(hy);
    float lz = v.z - __bfloat162float(hz), lw = v.w - __bfloat162float(hw);
    __nv_bfloat162* H = reinterpret_cast<__nv_bfloat162*>(hi + i4);
    __nv_bfloat162* L = reinterpret_cast<__nv_bfloat162*>(lo + i4);
    H[0] = __halves2bfloat162(hx, hy);
    H[1] = __halves2bfloat162(hz, hw);
    L[0] = __halves2bfloat162(__float2bfloat16(lx), __float2bfloat16(ly));
    L[1] = __halves2bfloat162(__float2bfloat16(lz), __float2bfloat16(lw));
}

// ---------------------------------------------------------------------------
// Pipelined tensor-core GEMM (3-term bf16 split), batched over relations.
// GRID = (RR, rowTiles): relation is the FAST dimension, so the 4 blocks
// sharing one A row-tile are adjacent in issue order -> A served from L2.
//   Y[(rel*NN + m), 0:BN] = rs_out_rel[m] * (A[m, :] @ W_rel[:, 0:BN])
// ---------------------------------------------------------------------------
template <int BN>
__global__ __launch_bounds__(256)
void gemm_bf16_pipe_kernel(const __nv_bfloat16* __restrict__ Ahi,
                           const __nv_bfloat16* __restrict__ Alo,
                           const __nv_bfloat16* __restrict__ Whi,
                           const __nv_bfloat16* __restrict__ Wlo,
                           const float* __restrict__ rs_out,
                           float* __restrict__ Y,
                           int M, int K) {
    constexpr int BM = 128;
    constexpr int BK = 16;
    constexpr int NT = BN / 16;
    constexpr int AS = BK + 8;
    constexpr int BS = BN + 8;
    constexpr int BCH = 2 * BN;       // 16-byte chunks per B tile

    __shared__ __align__(16) __nv_bfloat16 sAh[2][BM * AS], sAl[2][BM * AS];
    __shared__ __align__(16) __nv_bfloat16 sBh[2][BK * BS], sBl[2][BK * BS];

    const int t = threadIdx.x;
    const int lane = t & 31;
    const int wid = t >> 5;
    const int wm = wid & 3;
    const int wn = wid >> 2;
    const int rel = blockIdx.x;               // FAST dim: A-sharing blocks adjacent
    const int rowBase = blockIdx.y * BM;

    const __nv_bfloat16* WhiR = Whi + (size_t)rel * K * BN;
    const __nv_bfloat16* WloR = Wlo + (size_t)rel * K * BN;
    const float* rsR = rs_out + rel * NN;
    float* YR = Y + (size_t)rel * NN * BN;

    const int arow = t >> 1;
    const int acol = (t & 1) * 8;
    const int agr  = rowBase + arow;
    const bool apred = agr < M;
    const int brow = t / (BN / 8);
    const int bc8  = (t % (BN / 8)) * 8;

    float acc[2][NT][4];
#pragma unroll
    for (int mt = 0; mt < 2; ++mt)
#pragma unroll
        for (int nt = 0; nt < NT; ++nt)
#pragma unroll
            for (int j = 0; j < 4; ++j) acc[mt][nt][j] = 0.f;

    const int ntiles = K / BK;

    {
        cp_async16(&sAh[0][arow * AS + acol], Ahi + (size_t)agr * K + acol, apred);
        cp_async16(&sAl[0][arow * AS + acol], Alo + (size_t)agr * K + acol, apred);
        if (t < BCH) {
            cp_async16(&sBh[0][brow * BS + bc8], WhiR + (size_t)brow * BN + bc8, true);
            cp_async16(&sBl[0][brow * BS + bc8], WloR + (size_t)brow * BN + bc8, true);
        }
        cp_commit();
    }

    for (int tt = 0; tt < ntiles; ++tt) {
        int st = tt & 1;
        if (tt + 1 < ntiles) {
            int ns = st ^ 1;
            int k0 = (tt + 1) * BK;
            cp_async16(&sAh[ns][arow * AS + acol], Ahi + (size_t)agr * K + k0 + acol, apred);
            cp_async16(&sAl[ns][arow * AS + acol], Alo + (size_t)agr * K + k0 + acol, apred);
            if (t < BCH) {
                cp_async16(&sBh[ns][brow * BS + bc8], WhiR + (size_t)(k0 + brow) * BN + bc8, true);
                cp_async16(&sBl[ns][brow * BS + bc8], WloR + (size_t)(k0 + brow) * BN + bc8, true);
            }
            cp_commit();
            cp_wait<1>();
        } else {
            cp_wait<0>();
        }
        __syncthreads();

        uint32_t ah[2][4], al[2][4];
#pragma unroll
        for (int mt = 0; mt < 2; ++mt) {
            int row = wm * 32 + mt * 16 + (lane & 15);
            int col = (lane >> 4) * 8;
            ldsm_x4(ah[mt], (uint32_t)__cvta_generic_to_shared(&sAh[st][row * AS + col]));
            ldsm_x4(al[mt], (uint32_t)__cvta_generic_to_shared(&sAl[st][row * AS + col]));
        }
        uint32_t bh[NT][2], bl[NT][2];
#pragma unroll
        for (int nt = 0; nt < NT; ++nt) {
            int col = wn * (BN / 2) + nt * 8;
            int row = lane & 15;
            ldsm_x2t(bh[nt], (uint32_t)__cvta_generic_to_shared(&sBh[st][row * BS + col]));
            ldsm_x2t(bl[nt], (uint32_t)__cvta_generic_to_shared(&sBl[st][row * BS + col]));
        }
#pragma unroll
        for (int mt = 0; mt < 2; ++mt)
#pragma unroll
            for (int nt = 0; nt < NT; ++nt) {
                mma16816(acc[mt][nt], ah[mt], bh[nt]);
                mma16816(acc[mt][nt], al[mt], bh[nt]);
                mma16816(acc[mt][nt], ah[mt], bl[nt]);
            }
        __syncthreads();
    }

#pragma unroll
    for (int mt = 0; mt < 2; ++mt) {
        int gr0 = rowBase + wm * 32 + mt * 16 + (lane >> 2);
        int gc0 = wn * (BN / 2) + (lane & 3) * 2;
        float s0 = (gr0 < M)     ? __ldg(&rsR[gr0])     : 0.f;
        float s1 = (gr0 + 8 < M) ? __ldg(&rsR[gr0 + 8]) : 0.f;
#pragma unroll
        for (int nt = 0; nt < NT; ++nt) {
            int c = gc0 + nt * 8;
            if (gr0 < M)
                *reinterpret_cast<float2*>(YR + (size_t)gr0 * BN + c) =
                    make_float2(s0 * acc[mt][nt][0], s0 * acc[mt][nt][1]);
            if (gr0 + 8 < M)
                *reinterpret_cast<float2*>(YR + (size_t)(gr0 + 8) * BN + c) =
                    make_float2(s1 * acc[mt][nt][2], s1 * acc[mt][nt][3]);
        }
    }
}

// ---------------------------------------------------------------------------
// Layer-1 gather: warp per dst. shfl-batched edge records -> independent
// 512-B row gathers (MLP ~ degree). Fused bias + ReLU + bf16 split epilogue.
// ---------------------------------------------------------------------------
__global__ __launch_bounds__(256)
void gather_l1_kernel(const float* __restrict__ Y,
                      const int2* __restrict__ csr,
                      const int* __restrict__ offs,
                      const int* __restrict__ dcnt,
                      const float* __restrict__ b1,
                      __nv_bfloat16* __restrict__ a2hi,
                      __nv_bfloat16* __restrict__ a2lo) {
    int d = (blockIdx.x * blockDim.x + threadIdx.x) >> 5;
    if (d >= NN) return;
    int lane = threadIdx.x & 31;
    int n = dcnt[d];
    const int2* ep = csr + offs[d];

    float4 tot = make_float4(0.f, 0.f, 0.f, 0.f);
    for (int base = 0; base < n; base += 32) {
        int m = min(32, n - base);
        int2 rec = make_int2(0, 0);
        if (lane < m) rec = __ldg(ep + base + lane);
#pragma unroll 4
        for (int j = 0; j < m; ++j) {
            int yi  = __shfl_sync(0xffffffffu, rec.x, j);
            float c = __int_as_float(__shfl_sync(0xffffffffu, rec.y, j));
            float4 v = *reinterpret_cast<const float4*>(Y + (size_t)yi * HIDF + lane * 4);
            tot.x += c * v.x; tot.y += c * v.y;
            tot.z += c * v.z; tot.w += c * v.w;
        }
    }
#pragma unroll
    for (int r = 0; r < RR; ++r) {
        float4 bv = *reinterpret_cast<const float4*>(b1 + r * HIDF + lane * 4);
        tot.x += bv.x; tot.y += bv.y; tot.z += bv.z; tot.w += bv.w;
    }
    tot.x = fmaxf(tot.x, 0.f); tot.y = fmaxf(tot.y, 0.f);
    tot.z = fmaxf(tot.z, 0.f); tot.w = fmaxf(tot.w, 0.f);

    __nv_bfloat16 h0 = __float2bfloat16(tot.x), h1 = __float2bfloat16(tot.y);
    __nv_bfloat16 h2 = __float2bfloat16(tot.z), h3 = __float2bfloat16(tot.w);
    __nv_bfloat162 hA = __halves2bfloat162(h0, h1), hB = __halves2bfloat162(h2, h3);
    __nv_bfloat162 lA = __halves2bfloat162(__float2bfloat16(tot.x - __bfloat162float(h0)),
                                           __float2bfloat16(tot.y - __bfloat162float(h1)));
    __nv_bfloat162 lB = __halves2bfloat162(__float2bfloat16(tot.z - __bfloat162float(h2)),
                                           __float2bfloat16(tot.w - __bfloat162float(h3)));
    uint2 hv = make_uint2(*reinterpret_cast<uint32_t*>(&hA), *reinterpret_cast<uint32_t*>(&hB));
    uint2 lv = make_uint2(*reinterpret_cast<uint32_t*>(&lA), *reinterpret_cast<uint32_t*>(&lB));
    *reinterpret_cast<uint2*>(a2hi + (size_t)d * HIDF + lane * 4) = hv;
    *reinterpret_cast<uint2*>(a2lo + (size_t)d * HIDF + lane * 4) = lv;
}

// ---------------------------------------------------------------------------
// Layer-2 gather: warp per dst, 2 floats/lane. Fused bias; writes output.
// ---------------------------------------------------------------------------
__global__ __launch_bounds__(256)
void gather_l2_kernel(const float* __restrict__ Y,
                      const int2* __restrict__ csr,
                      const int* __restrict__ offs,
                      const int* __restrict__ dcnt,
                      const float* __restrict__ b2,
                      float* __restrict__ out) {
    int d = (blockIdx.x * blockDim.x + threadIdx.x) >> 5;
    if (d >= NN) return;
    int lane = threadIdx.x & 31;
    int n = dcnt[d];
    const int2* ep = csr + offs[d];

    float2 tot = make_float2(0.f, 0.f);
    for (int base = 0; base < n; base += 32) {
        int m = min(32, n - base);
        int2 rec = make_int2(0, 0);
        if (lane < m) rec = __ldg(ep + base + lane);
#pragma unroll 4
        for (int j = 0; j < m; ++j) {
            int yi  = __shfl_sync(0xffffffffu, rec.x, j);
            float c = __int_as_float(__shfl_sync(0xffffffffu, rec.y, j));
            float2 v = *reinterpret_cast<const float2*>(Y + (size_t)yi * OUTF + lane * 2);
            tot.x += c * v.x; tot.y += c * v.y;
        }
    }
#pragma unroll
    for (int r = 0; r < RR; ++r) {
        float2 bv = *reinterpret_cast<const float2*>(b2 + r * OUTF + lane * 2);
        tot.x += bv.x; tot.y += bv.y;
    }
    *reinterpret_cast<float2*>(out + (size_t)d * OUTF + lane * 2) = tot;
}

// ---------------------------------------------------------------------------
// Launch
// ---------------------------------------------------------------------------
extern "C" void kernel_launch(void* const* d_in, const int* in_sizes, int n_in,
                              void* d_out, int out_size) {
    const float* x    = (const float*)d_in[0];
    const int*   esrc = (const int*)  d_in[1];
    const int*   edst = (const int*)  d_in[2];
    const float* W1   = (const float*)d_in[3];
    const float* b1   = (const float*)d_in[4];
    const float* W2   = (const float*)d_in[5];
    const float* b2   = (const float*)d_in[6];
    float* out = (float*)d_out;

    __nv_bfloat16 *xhi, *xlo, *w1hi, *w1lo, *w2hi, *w2lo, *a2hi, *a2lo;
    float *Y1, *Y2, *rs_out, *rs_in;
    int *cnt, *offs, *dcnt, *cur;
    int2* csr;
    cudaGetSymbolAddress((void**)&xhi,    g_xhi);
    cudaGetSymbolAddress((void**)&xlo,    g_xlo);
    cudaGetSymbolAddress((void**)&w1hi,   g_w1hi);
    cudaGetSymbolAddress((void**)&w1lo,   g_w1lo);
    cudaGetSymbolAddress((void**)&w2hi,   g_w2hi);
    cudaGetSymbolAddress((void**)&w2lo,   g_w2lo);
    cudaGetSymbolAddress((void**)&a2hi,   g_a2hi);
    cudaGetSymbolAddress((void**)&a2lo,   g_a2lo);
    cudaGetSymbolAddress((void**)&Y1,     g_Y1);
    cudaGetSymbolAddress((void**)&Y2,     g_Y2);
    cudaGetSymbolAddress((void**)&cnt,    g_cnt);
    cudaGetSymbolAddress((void**)&rs_out, g_rs_out);
    cudaGetSymbolAddress((void**)&rs_in,  g_rs_in);
    cudaGetSymbolAddress((void**)&offs,   g_offs);
    cudaGetSymbolAddress((void**)&dcnt,   g_dcnt);
    cudaGetSymbolAddress((void**)&cur,    g_cur);
    cudaGetSymbolAddress((void**)&csr,    g_csr);

    int* cnt_out = cnt;
    int* cnt_in  = cnt + RR * NN;
    int* ctr     = cnt + 2 * RR * NN;

    const int TPB = 256;

    // ---- degrees + all-relation dst-CSR ----
    cudaMemsetAsync(cnt, 0, (2 * RR * NN + 1) * sizeof(int));   // one fused memset
    degree_count_kernel<<<(RR * EE + TPB - 1) / TPB, TPB>>>(esrc, edst, cnt_out, cnt_in);
    rs_kernel<<<(RR * NN + TPB - 1) / TPB, TPB>>>(cnt_out, cnt_in, rs_out, rs_in);
    alloc_offsets_kernel<<<(NN + TPB - 1) / TPB, TPB>>>(cnt_in, offs, dcnt, cur, ctr);
    csr_fill_kernel<<<(RR * EE + TPB - 1) / TPB, TPB>>>(esrc, edst, rs_in, cur, csr);

    // ---- bf16 splits of inputs/weights ----
    {
        int nx = NN * INF;
        split_kernel<<<(nx / 4 + TPB - 1) / TPB, TPB>>>(x, xhi, xlo, nx);
        int nw1 = RR * INF * HIDF;
        split_kernel<<<(nw1 / 4 + TPB - 1) / TPB, TPB>>>(W1, w1hi, w1lo, nw1);
        int nw2 = RR * HIDF * OUTF;
        split_kernel<<<(nw2 / 4 + TPB - 1) / TPB, TPB>>>(W2, w2hi, w2lo, nw2);
    }

    const dim3 gemmGrid(RR, (NN + 127) / 128);          // rel = fast dim (A L2-reuse)
    const int gatherGrid = (NN * 32 + TPB - 1) / TPB;   // warp per dst

    // ---- Layer 1: GEMM -> gather (bias+ReLU+split fused) ----
    gemm_bf16_pipe_kernel<HIDF><<<gemmGrid, TPB>>>(xhi, xlo, w1hi, w1lo, rs_out, Y1, NN, INF);
    gather_l1_kernel<<<gatherGrid, TPB>>>(Y1, csr, offs, dcnt, b1, a2hi, a2lo);

    // ---- Layer 2: GEMM -> gather (bias fused, writes out) ----
    gemm_bf16_pipe_kernel<OUTF><<<gemmGrid, TPB>>>(a2hi, a2lo, w2hi, w2lo, rs_out, Y2, NN, HIDF);
    gather_l2_kernel<<<gatherGrid, TPB>>>(Y2, csr, offs, dcnt, b2, out);
}

// round 14
// speedup vs baseline: 1.7761x; 1.0962x over previous
#include <cuda_runtime.h>
#include <cuda_bf16.h>
#include <cuda_fp16.h>
#include <cstdint>

// Problem constants
#define NN   100000   // nodes
#define RR   4        // relations
#define EE   500000   // edges per relation
#define INF  256
#define HIDF 128
#define OUTF 64

// ---------------------------------------------------------------------------
// Static device scratch (allocation-free per harness rules)
// ---------------------------------------------------------------------------
static __device__ __nv_bfloat16 g_xhi[(size_t)NN * INF];     // 51.2 MB
static __device__ __nv_bfloat16 g_xlo[(size_t)NN * INF];     // 51.2 MB
static __device__ __nv_bfloat16 g_w1hi[RR * INF * HIDF];
static __device__ __nv_bfloat16 g_w1lo[RR * INF * HIDF];
static __device__ __nv_bfloat16 g_w2hi[RR * HIDF * OUTF];
static __device__ __nv_bfloat16 g_w2lo[RR * HIDF * OUTF];
static __device__ __nv_bfloat16 g_a2hi[(size_t)NN * HIDF];   // 25.6 MB
static __device__ __nv_bfloat16 g_a2lo[(size_t)NN * HIDF];   // 25.6 MB
static __device__ __half g_Y1[(size_t)RR * NN * HIDF];       // 102.4 MB  [r*NN+n][128] fp16
static __device__ __half g_Y2[(size_t)RR * NN * OUTF];       //  51.2 MB  [r*NN+n][64]  fp16
// counters block: [cnt_out RR*NN | cnt_in RR*NN | ctr 1] -> single memset
static __device__ int   g_cnt[2 * RR * NN + 1];
static __device__ float g_rs_out[RR * NN];
static __device__ float g_rs_in[RR * NN];
static __device__ int   g_offs[NN];                          // dst-CSR segment starts (all rel)
static __device__ int   g_dcnt[NN];                          // total in-degree per dst
static __device__ int   g_cur[NN];                           // fill cursors
static __device__ int2  g_csr[(size_t)RR * EE];              // (r*NN+src, bits(rs_in_r[dst])) 16 MB

// ---------------------------------------------------------------------------
// Tensor-core / async-copy primitives
// ---------------------------------------------------------------------------
__device__ __forceinline__ void ldsm_x4(uint32_t* r, uint32_t a) {
    asm volatile("ldmatrix.sync.aligned.m8n8.x4.shared.b16 {%0,%1,%2,%3}, [%4];"
                 : "=r"(r[0]), "=r"(r[1]), "=r"(r[2]), "=r"(r[3]) : "r"(a));
}
__device__ __forceinline__ void ldsm_x2t(uint32_t* r, uint32_t a) {
    asm volatile("ldmatrix.sync.aligned.m8n8.x2.trans.shared.b16 {%0,%1}, [%2];"
                 : "=r"(r[0]), "=r"(r[1]) : "r"(a));
}
__device__ __forceinline__ void mma16816(float* c, const uint32_t* a, const uint32_t* b) {
    asm volatile(
        "mma.sync.aligned.m16n8k16.row.col.f32.bf16.bf16.f32 "
        "{%0,%1,%2,%3}, {%4,%5,%6,%7}, {%8,%9}, {%0,%1,%2,%3};"
        : "+f"(c[0]), "+f"(c[1]), "+f"(c[2]), "+f"(c[3])
        : "r"(a[0]), "r"(a[1]), "r"(a[2]), "r"(a[3]), "r"(b[0]), "r"(b[1]));
}
__device__ __forceinline__ void cp_async16(void* smem, const void* gmem, bool pred) {
    uint32_t s = (uint32_t)__cvta_generic_to_shared(smem);
    int sz = pred ? 16 : 0;
    asm volatile("cp.async.cg.shared.global [%0], [%1], 16, %2;"
                 :: "r"(s), "l"(gmem), "r"(sz));
}
__device__ __forceinline__ void cp_commit() {
    asm volatile("cp.async.commit_group;");
}
template <int N>
__device__ __forceinline__ void cp_wait() {
    asm volatile("cp.async.wait_group %0;" :: "n"(N));
}

// ---------------------------------------------------------------------------
// Preprocessing kernels
// ---------------------------------------------------------------------------
__global__ void degree_count_kernel(const int* __restrict__ src,
                                    const int* __restrict__ dst,
                                    int* __restrict__ cnt_out,
                                    int* __restrict__ cnt_in) {
    int i = blockIdx.x * blockDim.x + threadIdx.x;
    if (i >= RR * EE) return;
    int r = i / EE;
    atomicAdd(&cnt_out[r * NN + src[i]], 1);
    atomicAdd(&cnt_in [r * NN + dst[i]], 1);
}

__global__ void rs_kernel(const int* __restrict__ cnt_out,
                          const int* __restrict__ cnt_in,
                          float* __restrict__ rs_out,
                          float* __restrict__ rs_in) {
    int i = blockIdx.x * blockDim.x + threadIdx.x;
    if (i >= RR * NN) return;
    rs_out[i] = rsqrtf((float)max(cnt_out[i], 1));
    rs_in [i] = rsqrtf((float)max(cnt_in [i], 1));
}

// Segment per dst covering ALL relations; two-level bump allocation.
__global__ void alloc_offsets_kernel(const int* __restrict__ cnt_in,
                                     int* __restrict__ offs,
                                     int* __restrict__ dcnt,
                                     int* __restrict__ cur,
                                     int* __restrict__ ctr) {
    __shared__ int sctr, sbase;
    if (threadIdx.x == 0) sctr = 0;
    __syncthreads();
    int d = blockIdx.x * blockDim.x + threadIdx.x;
    int c = 0, local = 0;
    if (d < NN) {
        c = cnt_in[0 * NN + d] + cnt_in[1 * NN + d] +
            cnt_in[2 * NN + d] + cnt_in[3 * NN + d];
        local = atomicAdd(&sctr, c);
    }
    __syncthreads();
    if (threadIdx.x == 0) sbase = atomicAdd(ctr, sctr);
    __syncthreads();
    if (d < NN) {
        int off = sbase + local;
        offs[d] = off;
        dcnt[d] = c;
        cur[d]  = off;
    }
}

__global__ void csr_fill_kernel(const int* __restrict__ src,
                                const int* __restrict__ dst,
                                const float* __restrict__ rs_in,
                                int* __restrict__ cur,
                                int2* __restrict__ csr) {
    int i = blockIdx.x * blockDim.x + threadIdx.x;
    if (i >= RR * EE) return;
    int r = i / EE;
    int s = src[i];
    int d = dst[i];
    int pos = atomicAdd(&cur[d], 1);
    csr[pos] = make_int2(r * NN + s, __float_as_int(__ldg(&rs_in[r * NN + d])));
}

// Split fp32 -> (hi, lo) bf16 pair. n % 4 == 0.
__global__ void split_kernel(const float* __restrict__ in,
                             __nv_bfloat16* __restrict__ hi,
                             __nv_bfloat16* __restrict__ lo, int n) {
    int i4 = (blockIdx.x * blockDim.x + threadIdx.x) * 4;
    if (i4 >= n) return;
    float4 v = *reinterpret_cast<const float4*>(in + i4);
    __nv_bfloat16 hx = __float2bfloat16(v.x), hy = __float2bfloat16(v.y);
    __nv_bfloat16 hz = __float2bfloat16(v.z), hw = __float2bfloat16(v.w);
    float lx = v.x - __bfloat162float(hx), ly = v.y - __bfloat162float(hy);
    float lz = v.z - __bfloat162float(hz), lw = v.w - __bfloat162float(hw);
    __nv_bfloat162* H = reinterpret_cast<__nv_bfloat162*>(hi + i4);
    __nv_bfloat162* L = reinterpret_cast<__nv_bfloat162*>(lo + i4);
    H[0] = __halves2bfloat162(hx, hy);
    H[1] = __halves2bfloat162(hz, hw);
    L[0] = __halves2bfloat162(__float2bfloat16(lx), __float2bfloat16(ly));
    L[1] = __halves2bfloat162(__float2bfloat16(lz), __float2bfloat16(lw));
}

// ---------------------------------------------------------------------------
// Pipelined tensor-core GEMM (3-term bf16 split), batched over relations.
// GRID = (RR, rowTiles): relation fast -> A row-tile served from L2.
//   Y[(rel*NN + m), 0:BN] = fp16( rs_out_rel[m] * (A[m, :] @ W_rel[:, 0:BN]) )
// ---------------------------------------------------------------------------
template <int BN>
__global__ __launch_bounds__(256)
void gemm_bf16_pipe_kernel(const __nv_bfloat16* __restrict__ Ahi,
                           const __nv_bfloat16* __restrict__ Alo,
                           const __nv_bfloat16* __restrict__ Whi,
                           const __nv_bfloat16* __restrict__ Wlo,
                           const float* __restrict__ rs_out,
                           __half* __restrict__ Y,
                           int M, int K) {
    constexpr int BM = 128;
    constexpr int BK = 16;
    constexpr int NT = BN / 16;
    constexpr int AS = BK + 8;
    constexpr int BS = BN + 8;
    constexpr int BCH = 2 * BN;       // 16-byte chunks per B tile

    __shared__ __align__(16) __nv_bfloat16 sAh[2][BM * AS], sAl[2][BM * AS];
    __shared__ __align__(16) __nv_bfloat16 sBh[2][BK * BS], sBl[2][BK * BS];

    const int t = threadIdx.x;
    const int lane = t & 31;
    const int wid = t >> 5;
    const int wm = wid & 3;
    const int wn = wid >> 2;
    const int rel = blockIdx.x;               // FAST dim: A-sharing blocks adjacent
    const int rowBase = blockIdx.y * BM;

    const __nv_bfloat16* WhiR = Whi + (size_t)rel * K * BN;
    const __nv_bfloat16* WloR = Wlo + (size_t)rel * K * BN;
    const float* rsR = rs_out + rel * NN;
    __half* YR = Y + (size_t)rel * NN * BN;

    const int arow = t >> 1;
    const int acol = (t & 1) * 8;
    const int agr  = rowBase + arow;
    const bool apred = agr < M;
    const int brow = t / (BN / 8);
    const int bc8  = (t % (BN / 8)) * 8;

    float acc[2][NT][4];
#pragma unroll
    for (int mt = 0; mt < 2; ++mt)
#pragma unroll
        for (int nt = 0; nt < NT; ++nt)
#pragma unroll
            for (int j = 0; j < 4; ++j) acc[mt][nt][j] = 0.f;

    const int ntiles = K / BK;

    {
        cp_async16(&sAh[0][arow * AS + acol], Ahi + (size_t)agr * K + acol, apred);
        cp_async16(&sAl[0][arow * AS + acol], Alo + (size_t)agr * K + acol, apred);
        if (t < BCH) {
            cp_async16(&sBh[0][brow * BS + bc8], WhiR + (size_t)brow * BN + bc8, true);
            cp_async16(&sBl[0][brow * BS + bc8], WloR + (size_t)brow * BN + bc8, true);
        }
        cp_commit();
    }

    for (int tt = 0; tt < ntiles; ++tt) {
        int st = tt & 1;
        if (tt + 1 < ntiles) {
            int ns = st ^ 1;
            int k0 = (tt + 1) * BK;
            cp_async16(&sAh[ns][arow * AS + acol], Ahi + (size_t)agr * K + k0 + acol, apred);
            cp_async16(&sAl[ns][arow * AS + acol], Alo + (size_t)agr * K + k0 + acol, apred);
            if (t < BCH) {
                cp_async16(&sBh[ns][brow * BS + bc8], WhiR + (size_t)(k0 + brow) * BN + bc8, true);
                cp_async16(&sBl[ns][brow * BS + bc8], WloR + (size_t)(k0 + brow) * BN + bc8, true);
            }
            cp_commit();
            cp_wait<1>();
        } else {
            cp_wait<0>();
        }
        __syncthreads();

        uint32_t ah[2][4], al[2][4];
#pragma unroll
        for (int mt = 0; mt < 2; ++mt) {
            int row = wm * 32 + mt * 16 + (lane & 15);
            int col = (lane >> 4) * 8;
            ldsm_x4(ah[mt], (uint32_t)__cvta_generic_to_shared(&sAh[st][row * AS + col]));
            ldsm_x4(al[mt], (uint32_t)__cvta_generic_to_shared(&sAl[st][row * AS + col]));
        }
        uint32_t bh[NT][2], bl[NT][2];
#pragma unroll
        for (int nt = 0; nt < NT; ++nt) {
            int col = wn * (BN / 2) + nt * 8;
            int row = lane & 15;
            ldsm_x2t(bh[nt], (uint32_t)__cvta_generic_to_shared(&sBh[st][row * BS + col]));
            ldsm_x2t(bl[nt], (uint32_t)__cvta_generic_to_shared(&sBl[st][row * BS + col]));
        }
#pragma unroll
        for (int mt = 0; mt < 2; ++mt)
#pragma unroll
            for (int nt = 0; nt < NT; ++nt) {
                mma16816(acc[mt][nt], ah[mt], bh[nt]);
                mma16816(acc[mt][nt], al[mt], bh[nt]);
                mma16816(acc[mt][nt], ah[mt], bl[nt]);
            }
        __syncthreads();
    }

    // ---- epilogue: rs_out row-scale, fp16 pack, 4-byte stores
#pragma unroll
    for (int mt = 0; mt < 2; ++mt) {
        int gr0 = rowBase + wm * 32 + mt * 16 + (lane >> 2);
        int gc0 = wn * (BN / 2) + (lane & 3) * 2;
        float s0 = (gr0 < M)     ? __ldg(&rsR[gr0])     : 0.f;
        float s1 = (gr0 + 8 < M) ? __ldg(&rsR[gr0 + 8]) : 0.f;
#pragma unroll
        for (int nt = 0; nt < NT; ++nt) {
            int c = gc0 + nt * 8;
            if (gr0 < M)
                *reinterpret_cast<__half2*>(YR + (size_t)gr0 * BN + c) =
                    __floats2half2_rn(s0 * acc[mt][nt][0], s0 * acc[mt][nt][1]);
            if (gr0 + 8 < M)
                *reinterpret_cast<__half2*>(YR + (size_t)(gr0 + 8) * BN + c) =
                    __floats2half2_rn(s1 * acc[mt][nt][2], s1 * acc[mt][nt][3]);
        }
    }
}

// ---------------------------------------------------------------------------
// Layer-1 gather: warp per dst, fp16 Y rows (256 B), fp32 accumulation.
// Fused bias + ReLU + bf16 split epilogue.
// ---------------------------------------------------------------------------
__global__ __launch_bounds__(256)
void gather_l1_kernel(const __half* __restrict__ Y,
                      const int2* __restrict__ csr,
                      const int* __restrict__ offs,
                      const int* __restrict__ dcnt,
                      const float* __restrict__ b1,
                      __nv_bfloat16* __restrict__ a2hi,
                      __nv_bfloat16* __restrict__ a2lo) {
    int d = (blockIdx.x * blockDim.x + threadIdx.x) >> 5;
    if (d >= NN) return;
    int lane = threadIdx.x & 31;
    int n = dcnt[d];
    const int2* ep = csr + offs[d];

    float4 tot = make_float4(0.f, 0.f, 0.f, 0.f);
    for (int base = 0; base < n; base += 32) {
        int m = min(32, n - base);
        int2 rec = make_int2(0, 0);
        if (lane < m) rec = __ldg(ep + base + lane);
#pragma unroll 4
        for (int j = 0; j < m; ++j) {
            int yi  = __shfl_sync(0xffffffffu, rec.x, j);
            float c = __int_as_float(__shfl_sync(0xffffffffu, rec.y, j));
            uint2 raw = *reinterpret_cast<const uint2*>(Y + (size_t)yi * HIDF + lane * 4);
            float2 f0 = __half22float2(*reinterpret_cast<__half2*>(&raw.x));
            float2 f1 = __half22float2(*reinterpret_cast<__half2*>(&raw.y));
            tot.x += c * f0.x; tot.y += c * f0.y;
            tot.z += c * f1.x; tot.w += c * f1.y;
        }
    }
#pragma unroll
    for (int r = 0; r < RR; ++r) {
        float4 bv = *reinterpret_cast<const float4*>(b1 + r * HIDF + lane * 4);
        tot.x += bv.x; tot.y += bv.y; tot.z += bv.z; tot.w += bv.w;
    }
    tot.x = fmaxf(tot.x, 0.f); tot.y = fmaxf(tot.y, 0.f);
    tot.z = fmaxf(tot.z, 0.f); tot.w = fmaxf(tot.w, 0.f);

    __nv_bfloat16 h0 = __float2bfloat16(tot.x), h1 = __float2bfloat16(tot.y);
    __nv_bfloat16 h2 = __float2bfloat16(tot.z), h3 = __float2bfloat16(tot.w);
    __nv_bfloat162 hA = __halves2bfloat162(h0, h1), hB = __halves2bfloat162(h2, h3);
    __nv_bfloat162 lA = __halves2bfloat162(__float2bfloat16(tot.x - __bfloat162float(h0)),
                                           __float2bfloat16(tot.y - __bfloat162float(h1)));
    __nv_bfloat162 lB = __halves2bfloat162(__float2bfloat16(tot.z - __bfloat162float(h2)),
                                           __float2bfloat16(tot.w - __bfloat162float(h3)));
    uint2 hv = make_uint2(*reinterpret_cast<uint32_t*>(&hA), *reinterpret_cast<uint32_t*>(&hB));
    uint2 lv = make_uint2(*reinterpret_cast<uint32_t*>(&lA), *reinterpret_cast<uint32_t*>(&lB));
    *reinterpret_cast<uint2*>(a2hi + (size_t)d * HIDF + lane * 4) = hv;
    *reinterpret_cast<uint2*>(a2lo + (size_t)d * HIDF + lane * 4) = lv;
}

// ---------------------------------------------------------------------------
// Layer-2 gather: warp per dst, fp16 Y rows (128 B). Fused bias; writes out.
// ---------------------------------------------------------------------------
__global__ __launch_bounds__(256)
void gather_l2_kernel(const __half* __restrict__ Y,
                      const int2* __restrict__ csr,
                      const int* __restrict__ offs,
                      const int* __restrict__ dcnt,
                      const float* __restrict__ b2,
                      float* __restrict__ out) {
    int d = (blockIdx.x * blockDim.x + threadIdx.x) >> 5;
    if (d >= NN) return;
    int lane = threadIdx.x & 31;
    int n = dcnt[d];
    const int2* ep = csr + offs[d];

    float2 tot = make_float2(0.f, 0.f);
    for (int base = 0; base < n; base += 32) {
        int m = min(32, n - base);
        int2 rec = make_int2(0, 0);
        if (lane < m) rec = __ldg(ep + base + lane);
#pragma unroll 4
        for (int j = 0; j < m; ++j) {
            int yi  = __shfl_sync(0xffffffffu, rec.x, j);
            float c = __int_as_float(__shfl_sync(0xffffffffu, rec.y, j));
            uint32_t raw = *reinterpret_cast<const uint32_t*>(Y + (size_t)yi * OUTF + lane * 2);
            float2 v = __half22float2(*reinterpret_cast<__half2*>(&raw));
            tot.x += c * v.x; tot.y += c * v.y;
        }
    }
#pragma unroll
    for (int r = 0; r < RR; ++r) {
        float2 bv = *reinterpret_cast<const float2*>(b2 + r * OUTF + lane * 2);
        tot.x += bv.x; tot.y += bv.y;
    }
    *reinterpret_cast<float2*>(out + (size_t)d * OUTF + lane * 2) = tot;
}

// ---------------------------------------------------------------------------
// Launch
// ---------------------------------------------------------------------------
extern "C" void kernel_launch(void* const* d_in, const int* in_sizes, int n_in,
                              void* d_out, int out_size) {
    const float* x    = (const float*)d_in[0];
    const int*   esrc = (const int*)  d_in[1];
    const int*   edst = (const int*)  d_in[2];
    const float* W1   = (const float*)d_in[3];
    const float* b1   = (const float*)d_in[4];
    const float* W2   = (const float*)d_in[5];
    const float* b2   = (const float*)d_in[6];
    float* out = (float*)d_out;

    __nv_bfloat16 *xhi, *xlo, *w1hi, *w1lo, *w2hi, *w2lo, *a2hi, *a2lo;
    __half *Y1, *Y2;
    float *rs_out, *rs_in;
    int *cnt, *offs, *dcnt, *cur;
    int2* csr;
    cudaGetSymbolAddress((void**)&xhi,    g_xhi);
    cudaGetSymbolAddress((void**)&xlo,    g_xlo);
    cudaGetSymbolAddress((void**)&w1hi,   g_w1hi);
    cudaGetSymbolAddress((void**)&w1lo,   g_w1lo);
    cudaGetSymbolAddress((void**)&w2hi,   g_w2hi);
    cudaGetSymbolAddress((void**)&w2lo,   g_w2lo);
    cudaGetSymbolAddress((void**)&a2hi,   g_a2hi);
    cudaGetSymbolAddress((void**)&a2lo,   g_a2lo);
    cudaGetSymbolAddress((void**)&Y1,     g_Y1);
    cudaGetSymbolAddress((void**)&Y2,     g_Y2);
    cudaGetSymbolAddress((void**)&cnt,    g_cnt);
    cudaGetSymbolAddress((void**)&rs_out, g_rs_out);
    cudaGetSymbolAddress((void**)&rs_in,  g_rs_in);
    cudaGetSymbolAddress((void**)&offs,   g_offs);
    cudaGetSymbolAddress((void**)&dcnt,   g_dcnt);
    cudaGetSymbolAddress((void**)&cur,    g_cur);
    cudaGetSymbolAddress((void**)&csr,    g_csr);

    int* cnt_out = cnt;
    int* cnt_in  = cnt + RR * NN;
    int* ctr     = cnt + 2 * RR * NN;

    const int TPB = 256;

    // ---- degrees + all-relation dst-CSR ----
    cudaMemsetAsync(cnt, 0, (2 * RR * NN + 1) * sizeof(int));
    degree_count_kernel<<<(RR * EE + TPB - 1) / TPB, TPB>>>(esrc, edst, cnt_out, cnt_in);
    rs_kernel<<<(RR * NN + TPB - 1) / TPB, TPB>>>(cnt_out, cnt_in, rs_out, rs_in);
    alloc_offsets_kernel<<<(NN + TPB - 1) / TPB, TPB>>>(cnt_in, offs, dcnt, cur, ctr);
    csr_fill_kernel<<<(RR * EE + TPB - 1) / TPB, TPB>>>(esrc, edst, rs_in, cur, csr);

    // ---- bf16 splits of inputs/weights ----
    {
        int nx = NN * INF;
        split_kernel<<<(nx / 4 + TPB - 1) / TPB, TPB>>>(x, xhi, xlo, nx);
        int nw1 = RR * INF * HIDF;
        split_kernel<<<(nw1 / 4 + TPB - 1) / TPB, TPB>>>(W1, w1hi, w1lo, nw1);
        int nw2 = RR * HIDF * OUTF;
        split_kernel<<<(nw2 / 4 + TPB - 1) / TPB, TPB>>>(W2, w2hi, w2lo, nw2);
    }

    const dim3 gemmGrid(RR, (NN + 127) / 128);          // rel = fast dim (A L2-reuse)
    const int gatherGrid = (NN * 32 + TPB - 1) / TPB;   // warp per dst

    // ---- Layer 1: GEMM -> gather (bias+ReLU+split fused) ----
    gemm_bf16_pipe_kernel<HIDF><<<gemmGrid, TPB>>>(xhi, xlo, w1hi, w1lo, rs_out, Y1, NN, INF);
    gather_l1_kernel<<<gatherGrid, TPB>>>(Y1, csr, offs, dcnt, b1, a2hi, a2lo);

    // ---- Layer 2: GEMM -> gather (bias fused, writes out) ----
    gemm_bf16_pipe_kernel<OUTF><<<gemmGrid, TPB>>>(a2hi, a2lo, w2hi, w2lo, rs_out, Y2, NN, HIDF);
    gather_l2_kernel<<<gatherGrid, TPB>>>(Y2, csr, offs, dcnt, b2, out);
}